// round 1
// baseline (speedup 1.0000x reference)
#include <cuda_runtime.h>
#include <math.h>

#define S_LEN   2048
#define D_MODEL 1024
#define NHEAD   16
#define DK      64
#define BATCH   2
#define MTOT    (BATCH * S_LEN)      // 4096

// Scratch (allocation-free rule: __device__ globals)
__device__ float g_Q[BATCH * NHEAD * S_LEN * DK];   // [B,H,S,dk]
__device__ float g_K[BATCH * NHEAD * S_LEN * DK];
__device__ float g_V[BATCH * NHEAD * S_LEN * DK];
__device__ float g_C[BATCH * S_LEN * D_MODEL];      // context [B,S,D]

// ---------------------------------------------------------------------------
// SGEMM: C = A[M,K] @ W[N,K]^T   (both row-major, "NT")
// BM=BN=128, BK=16, 256 threads, 8x8 per thread.
// REMAP=true scatters output (m,n) -> [b,h,s,d] layout for Q/K/V.
// ---------------------------------------------------------------------------
template<bool REMAP>
__global__ __launch_bounds__(256, 2)
void gemm_nt(const float* __restrict__ A, const float* __restrict__ W,
             float* __restrict__ C, int M, int N, int K)
{
    __shared__ float As[16][132];   // [k][m], padded
    __shared__ float Bs[16][132];   // [k][n]

    const int tid = threadIdx.x;
    const int ty = tid >> 4, tx = tid & 15;
    const int r0 = ty * 8, c0 = tx * 8;
    const int mBase = blockIdx.y * 128;
    const int nBase = blockIdx.x * 128;

    float acc[8][8];
#pragma unroll
    for (int i = 0; i < 8; i++)
#pragma unroll
        for (int j = 0; j < 8; j++) acc[i][j] = 0.f;

    for (int k0 = 0; k0 < K; k0 += 16) {
#pragma unroll
        for (int i = 0; i < 2; i++) {
            int idx = tid + i * 256;           // 0..511
            int row = idx >> 2;                // 0..127
            int c4  = (idx & 3) * 4;           // 0,4,8,12
            float4 va = *(const float4*)&A[(size_t)(mBase + row) * K + k0 + c4];
            As[c4 + 0][row] = va.x; As[c4 + 1][row] = va.y;
            As[c4 + 2][row] = va.z; As[c4 + 3][row] = va.w;
            float4 vw = *(const float4*)&W[(size_t)(nBase + row) * K + k0 + c4];
            Bs[c4 + 0][row] = vw.x; Bs[c4 + 1][row] = vw.y;
            Bs[c4 + 2][row] = vw.z; Bs[c4 + 3][row] = vw.w;
        }
        __syncthreads();

#pragma unroll
        for (int kk = 0; kk < 16; kk++) {
            float a[8], b[8];
            *(float4*)&a[0] = *(float4*)&As[kk][r0];
            *(float4*)&a[4] = *(float4*)&As[kk][r0 + 4];
            *(float4*)&b[0] = *(float4*)&Bs[kk][c0];
            *(float4*)&b[4] = *(float4*)&Bs[kk][c0 + 4];
#pragma unroll
            for (int i = 0; i < 8; i++)
#pragma unroll
                for (int j = 0; j < 8; j++) acc[i][j] += a[i] * b[j];
        }
        __syncthreads();
    }

    if (REMAP) {
        // (m, n) -> out[b][h][s][d], b=m/S, s=m%S, h=n/64, d=n%64
        int n0 = nBase + c0;
        int h  = n0 >> 6, d0 = n0 & 63;
        int m0 = mBase + r0;
        int b  = m0 >> 11, s0 = m0 & (S_LEN - 1);
        float* out = C + (((size_t)b * NHEAD + h) * S_LEN + s0) * DK + d0;
#pragma unroll
        for (int i = 0; i < 8; i++) {
#pragma unroll
            for (int j = 0; j < 8; j += 4) {
                float4 v = make_float4(acc[i][j], acc[i][j+1], acc[i][j+2], acc[i][j+3]);
                *(float4*)&out[(size_t)i * DK + j] = v;
            }
        }
    } else {
        float* out = C + (size_t)(mBase + r0) * N + nBase + c0;
#pragma unroll
        for (int i = 0; i < 8; i++) {
#pragma unroll
            for (int j = 0; j < 8; j += 4) {
                float4 v = make_float4(acc[i][j], acc[i][j+1], acc[i][j+2], acc[i][j+3]);
                *(float4*)&out[(size_t)i * N + j] = v;
            }
        }
    }
}

// ---------------------------------------------------------------------------
// Flash attention, causal. One block per (q-tile of 64 rows, b*h).
// 256 threads, 4x4 register microtiles. dk = Bc = Br = 64.
// Q,K stored transposed in smem ([d][r]); S stored [j][r]; V natural [j][d].
// Output written directly in [B,S,D] layout.
// ---------------------------------------------------------------------------
#define SMEM_STRIDE 68
#define LOG2E 1.4426950408889634f

__global__ __launch_bounds__(256, 2)
void attn_kernel(const float* __restrict__ Q, const float* __restrict__ K,
                 const float* __restrict__ V, float* __restrict__ Out)
{
    extern __shared__ float smem[];
    float* sQ = smem;                       // [d][r] 64*68
    float* sK = sQ + 64 * SMEM_STRIDE;      // [d][c]
    float* sV = sK + 64 * SMEM_STRIDE;      // [j][d]
    float* sS = sV + 64 * SMEM_STRIDE;      // [j][r]
    float* sm = sS + 64 * SMEM_STRIDE;      // [64] running max
    float* sl = sm + 64;                    // [64] running sum
    float* sc = sl + 64;                    // [64] correction

    const int tid = threadIdx.x;
    const int ty = tid >> 4, tx = tid & 15;
    const int r0 = ty * 4, c0 = tx * 4;
    const int qt = blockIdx.x;              // q tile
    const int bh = blockIdx.y;              // b*NHEAD + h
    const int q0 = qt * 64;

    const size_t base = (size_t)bh * S_LEN * DK;
    const float* Qp = Q + base;
    const float* Kp = K + base;
    const float* Vp = V + base;

    // Load Q tile transposed: sQ[d][r]
#pragma unroll
    for (int i = 0; i < 4; i++) {
        int idx = tid + i * 256;            // 0..1023
        int r  = idx >> 4;                  // 0..63
        int d4 = (idx & 15) * 4;
        float4 v = *(const float4*)&Qp[(size_t)(q0 + r) * DK + d4];
        sQ[(d4 + 0) * SMEM_STRIDE + r] = v.x;
        sQ[(d4 + 1) * SMEM_STRIDE + r] = v.y;
        sQ[(d4 + 2) * SMEM_STRIDE + r] = v.z;
        sQ[(d4 + 3) * SMEM_STRIDE + r] = v.w;
    }
    if (tid < 64) { sm[tid] = -1e30f; sl[tid] = 0.f; }

    float acc[4][4];
#pragma unroll
    for (int i = 0; i < 4; i++)
#pragma unroll
        for (int j = 0; j < 4; j++) acc[i][j] = 0.f;

    for (int jt = 0; jt <= qt; jt++) {
        const int j0 = jt * 64;
        __syncthreads();  // protect previous iter's reads of sK/sV/sS
        // Load K (transposed) and V (natural)
#pragma unroll
        for (int i = 0; i < 4; i++) {
            int idx = tid + i * 256;
            int r  = idx >> 4;
            int d4 = (idx & 15) * 4;
            float4 vk = *(const float4*)&Kp[(size_t)(j0 + r) * DK + d4];
            sK[(d4 + 0) * SMEM_STRIDE + r] = vk.x;
            sK[(d4 + 1) * SMEM_STRIDE + r] = vk.y;
            sK[(d4 + 2) * SMEM_STRIDE + r] = vk.z;
            sK[(d4 + 3) * SMEM_STRIDE + r] = vk.w;
            float4 vv = *(const float4*)&Vp[(size_t)(j0 + r) * DK + d4];
            *(float4*)&sV[r * SMEM_STRIDE + d4] = vv;
        }
        __syncthreads();

        // S = Q K^T  (4x4 microtile per thread)
        float sv[4][4];
#pragma unroll
        for (int i = 0; i < 4; i++)
#pragma unroll
            for (int j = 0; j < 4; j++) sv[i][j] = 0.f;
#pragma unroll 4
        for (int d = 0; d < 64; d++) {
            float4 q4 = *(float4*)&sQ[d * SMEM_STRIDE + r0];
            float4 k4 = *(float4*)&sK[d * SMEM_STRIDE + c0];
            float qa[4] = {q4.x, q4.y, q4.z, q4.w};
            float kb[4] = {k4.x, k4.y, k4.z, k4.w};
#pragma unroll
            for (int i = 0; i < 4; i++)
#pragma unroll
                for (int j = 0; j < 4; j++) sv[i][j] += qa[i] * kb[j];
        }
        const float scale = 0.125f;  // 1/sqrt(64)
#pragma unroll
        for (int i = 0; i < 4; i++)
#pragma unroll
            for (int j = 0; j < 4; j++) {
                float s = sv[i][j] * scale;
                if (jt == qt && (c0 + j) > (r0 + i)) s = -1e30f;
                sS[(c0 + j) * SMEM_STRIDE + (r0 + i)] = s;
            }
        __syncthreads();

        // Online softmax: one thread per query row
        if (tid < 64) {
            int r = tid;
            float mo = sm[r];
            float mx = mo;
#pragma unroll 8
            for (int j = 0; j < 64; j++)
                mx = fmaxf(mx, sS[j * SMEM_STRIDE + r]);
            float cf = exp2f((mo - mx) * LOG2E);
            float sum = 0.f;
#pragma unroll 8
            for (int j = 0; j < 64; j++) {
                float p = exp2f((sS[j * SMEM_STRIDE + r] - mx) * LOG2E);
                sS[j * SMEM_STRIDE + r] = p;
                sum += p;
            }
            sl[r] = sl[r] * cf + sum;
            sm[r] = mx;
            sc[r] = cf;
        }
        __syncthreads();

        // Rescale accumulator, then O += P V
        float cf[4];
#pragma unroll
        for (int i = 0; i < 4; i++) cf[i] = sc[r0 + i];
#pragma unroll
        for (int i = 0; i < 4; i++)
#pragma unroll
            for (int j = 0; j < 4; j++) acc[i][j] *= cf[i];
#pragma unroll 4
        for (int jj = 0; jj < 64; jj++) {
            float4 p4 = *(float4*)&sS[jj * SMEM_STRIDE + r0];
            float4 v4 = *(float4*)&sV[jj * SMEM_STRIDE + c0];
            float pa[4] = {p4.x, p4.y, p4.z, p4.w};
            float vb[4] = {v4.x, v4.y, v4.z, v4.w};
#pragma unroll
            for (int i = 0; i < 4; i++)
#pragma unroll
                for (int j = 0; j < 4; j++) acc[i][j] += pa[i] * vb[j];
        }
    }

    // Epilogue: normalize, write context in [B,S,D] layout
    float inv[4];
#pragma unroll
    for (int i = 0; i < 4; i++) inv[i] = 1.f / sl[r0 + i];

    const int b = bh >> 4;           // / NHEAD
    const int h = bh & 15;           // % NHEAD
    float* out = Out + ((size_t)b * S_LEN + q0 + r0) * D_MODEL + h * DK + c0;
#pragma unroll
    for (int i = 0; i < 4; i++) {
        float4 v = make_float4(acc[i][0] * inv[i], acc[i][1] * inv[i],
                               acc[i][2] * inv[i], acc[i][3] * inv[i]);
        *(float4*)&out[(size_t)i * D_MODEL] = v;
    }
}

// ---------------------------------------------------------------------------
extern "C" void kernel_launch(void* const* d_in, const int* in_sizes, int n_in,
                              void* d_out, int out_size)
{
    const float* x  = (const float*)d_in[0];
    const float* Wq = (const float*)d_in[1];
    const float* Wk = (const float*)d_in[2];
    const float* Wv = (const float*)d_in[3];
    const float* Wo = (const float*)d_in[4];
    float* out = (float*)d_out;

    float *pQ, *pK, *pV, *pC;
    cudaGetSymbolAddress((void**)&pQ, g_Q);
    cudaGetSymbolAddress((void**)&pK, g_K);
    cudaGetSymbolAddress((void**)&pV, g_V);
    cudaGetSymbolAddress((void**)&pC, g_C);

    const int attn_smem = (4 * 64 * SMEM_STRIDE + 3 * 64) * sizeof(float);
    cudaFuncSetAttribute(attn_kernel, cudaFuncAttributeMaxDynamicSharedMemorySize,
                         attn_smem);

    dim3 gGrid(D_MODEL / 128, MTOT / 128);   // (8, 32)
    gemm_nt<true><<<gGrid, 256>>>(x, Wq, pQ, MTOT, D_MODEL, D_MODEL);
    gemm_nt<true><<<gGrid, 256>>>(x, Wk, pK, MTOT, D_MODEL, D_MODEL);
    gemm_nt<true><<<gGrid, 256>>>(x, Wv, pV, MTOT, D_MODEL, D_MODEL);

    dim3 aGrid(S_LEN / 64, BATCH * NHEAD);   // (32, 32)
    attn_kernel<<<aGrid, 256, attn_smem>>>(pQ, pK, pV, pC);

    gemm_nt<false><<<gGrid, 256>>>(pC, Wo, out, MTOT, D_MODEL, D_MODEL);
}

// round 3
// speedup vs baseline: 1.0159x; 1.0159x over previous
#include <cuda_runtime.h>
#include <math.h>

#define S_LEN   2048
#define D_MODEL 1024
#define NHEAD   16
#define DK      64
#define BATCH   2
#define MTOT    (BATCH * S_LEN)      // 4096

// Scratch (allocation-free rule: __device__ globals)
__device__ float g_Q[BATCH * NHEAD * S_LEN * DK];   // [B,H,S,dk]
__device__ float g_K[BATCH * NHEAD * S_LEN * DK];
__device__ float g_V[BATCH * NHEAD * S_LEN * DK];
__device__ float g_C[BATCH * S_LEN * D_MODEL];      // context [B,S,D]

// ---------------------------------------------------------------------------
// SGEMM body: C = A[M,K] @ W[N,K]^T, double-buffered smem, 128x128x16 tile,
// 256 threads, 8x8 per thread. REMAP scatters to [B,H,S,dk].
// ---------------------------------------------------------------------------
struct SmemGemm {
    float As[2][16][132];
    float Bs[2][16][132];
};

template<bool REMAP>
__device__ __forceinline__
void gemm_body(const float* __restrict__ A, const float* __restrict__ W,
               float* __restrict__ C, int M, int N, int K,
               int mBase, int nBase, SmemGemm* sm)
{
    const int tid = threadIdx.x;
    const int ty = tid >> 4, tx = tid & 15;
    const int r0 = ty * 8, c0 = tx * 8;

    // loader indices (each thread: 2 rows worth of 4 contiguous k's)
    const int lrow0 = tid >> 2;               // 0..63
    const int lc4   = (tid & 3) * 4;          // 0,4,8,12

    float4 pa[2], pw[2];

    auto loadRegs = [&](int k0) {
#pragma unroll
        for (int i = 0; i < 2; i++) {
            int row = lrow0 + i * 64;
            pa[i] = *(const float4*)&A[(size_t)(mBase + row) * K + k0 + lc4];
            pw[i] = *(const float4*)&W[(size_t)(nBase + row) * K + k0 + lc4];
        }
    };
    auto stsRegs = [&](int b) {
#pragma unroll
        for (int i = 0; i < 2; i++) {
            int row = lrow0 + i * 64;
            sm->As[b][lc4 + 0][row] = pa[i].x; sm->As[b][lc4 + 1][row] = pa[i].y;
            sm->As[b][lc4 + 2][row] = pa[i].z; sm->As[b][lc4 + 3][row] = pa[i].w;
            sm->Bs[b][lc4 + 0][row] = pw[i].x; sm->Bs[b][lc4 + 1][row] = pw[i].y;
            sm->Bs[b][lc4 + 2][row] = pw[i].z; sm->Bs[b][lc4 + 3][row] = pw[i].w;
        }
    };

    float acc[8][8];
#pragma unroll
    for (int i = 0; i < 8; i++)
#pragma unroll
        for (int j = 0; j < 8; j++) acc[i][j] = 0.f;

    loadRegs(0);
    stsRegs(0);
    __syncthreads();

    int buf = 0;
    for (int k0 = 0; k0 < K; k0 += 16) {
        const int nk = k0 + 16;
        if (nk < K) loadRegs(nk);

#pragma unroll
        for (int kk = 0; kk < 16; kk++) {
            float a[8], b[8];
            *(float4*)&a[0] = *(float4*)&sm->As[buf][kk][r0];
            *(float4*)&a[4] = *(float4*)&sm->As[buf][kk][r0 + 4];
            *(float4*)&b[0] = *(float4*)&sm->Bs[buf][kk][c0];
            *(float4*)&b[4] = *(float4*)&sm->Bs[buf][kk][c0 + 4];
#pragma unroll
            for (int i = 0; i < 8; i++)
#pragma unroll
                for (int j = 0; j < 8; j++) acc[i][j] += a[i] * b[j];
        }

        if (nk < K) {
            stsRegs(buf ^ 1);
            __syncthreads();
            buf ^= 1;
        }
    }

    if (REMAP) {
        int n0 = nBase + c0;
        int h  = n0 >> 6, d0 = n0 & 63;
        int m0 = mBase + r0;
        int b  = m0 >> 11, s0 = m0 & (S_LEN - 1);
        float* out = C + (((size_t)b * NHEAD + h) * S_LEN + s0) * DK + d0;
#pragma unroll
        for (int i = 0; i < 8; i++) {
#pragma unroll
            for (int j = 0; j < 8; j += 4) {
                float4 v = make_float4(acc[i][j], acc[i][j+1], acc[i][j+2], acc[i][j+3]);
                *(float4*)&out[(size_t)i * DK + j] = v;
            }
        }
    } else {
        float* out = C + (size_t)(mBase + r0) * N + nBase + c0;
#pragma unroll
        for (int i = 0; i < 8; i++) {
#pragma unroll
            for (int j = 0; j < 8; j += 4) {
                float4 v = make_float4(acc[i][j], acc[i][j+1], acc[i][j+2], acc[i][j+3]);
                *(float4*)&out[(size_t)i * N + j] = v;
            }
        }
    }
}

// Fused Q/K/V projection: blockIdx.z selects the weight/output.
__global__ __launch_bounds__(256, 2)
void gemm_qkv(const float* __restrict__ A,
              const float* __restrict__ W0, const float* __restrict__ W1,
              const float* __restrict__ W2,
              float* __restrict__ C0, float* __restrict__ C1,
              float* __restrict__ C2, int M, int N, int K)
{
    __shared__ SmemGemm sm;
    const float* W = (blockIdx.z == 0) ? W0 : (blockIdx.z == 1) ? W1 : W2;
    float*       C = (blockIdx.z == 0) ? C0 : (blockIdx.z == 1) ? C1 : C2;
    gemm_body<true>(A, W, C, M, N, K, blockIdx.y * 128, blockIdx.x * 128, &sm);
}

__global__ __launch_bounds__(256, 2)
void gemm_out(const float* __restrict__ A, const float* __restrict__ W,
              float* __restrict__ C, int M, int N, int K)
{
    __shared__ SmemGemm sm;
    gemm_body<false>(A, W, C, M, N, K, blockIdx.y * 128, blockIdx.x * 128, &sm);
}

// ---------------------------------------------------------------------------
// Flash attention, causal. Register-resident softmax with shuffle reductions.
// Br=Bc=64, 256 threads, 4x4 microtiles. qt reversed (largest blocks first).
// ---------------------------------------------------------------------------
#define SMEM_STRIDE 68
#define LOG2E 1.4426950408889634f

__global__ __launch_bounds__(256, 2)
void attn_kernel(const float* __restrict__ Q, const float* __restrict__ K,
                 const float* __restrict__ V, float* __restrict__ Out)
{
    extern __shared__ float smem[];
    float* sQ = smem;                       // [d][r]
    float* sK = sQ + 64 * SMEM_STRIDE;      // [d][c]
    float* sV = sK + 64 * SMEM_STRIDE;      // [j][d]
    float* sS = sV + 64 * SMEM_STRIDE;      // [c][r]  (P transposed)

    const int tid = threadIdx.x;
    const int ty = tid >> 4, tx = tid & 15;
    const int r0 = ty * 4, c0 = tx * 4;
    const int qt = gridDim.x - 1 - blockIdx.x;   // largest-first
    const int bh = blockIdx.y;
    const int q0 = qt * 64;

    const size_t base = (size_t)bh * S_LEN * DK;
    const float* Qp = Q + base;
    const float* Kp = K + base;
    const float* Vp = V + base;

    // Load Q tile transposed: sQ[d][r]
#pragma unroll
    for (int i = 0; i < 4; i++) {
        int idx = tid + i * 256;
        int r  = idx >> 4;
        int d4 = (idx & 15) * 4;
        float4 v = *(const float4*)&Qp[(size_t)(q0 + r) * DK + d4];
        sQ[(d4 + 0) * SMEM_STRIDE + r] = v.x;
        sQ[(d4 + 1) * SMEM_STRIDE + r] = v.y;
        sQ[(d4 + 2) * SMEM_STRIDE + r] = v.z;
        sQ[(d4 + 3) * SMEM_STRIDE + r] = v.w;
    }

    float m_run[4], l_run[4];
#pragma unroll
    for (int i = 0; i < 4; i++) { m_run[i] = -1e30f; l_run[i] = 0.f; }

    float acc[4][4];
#pragma unroll
    for (int i = 0; i < 4; i++)
#pragma unroll
        for (int j = 0; j < 4; j++) acc[i][j] = 0.f;

    for (int jt = 0; jt <= qt; jt++) {
        const int j0 = jt * 64;
        __syncthreads();  // prev iter done reading sK/sV/sS
#pragma unroll
        for (int i = 0; i < 4; i++) {
            int idx = tid + i * 256;
            int r  = idx >> 4;
            int d4 = (idx & 15) * 4;
            float4 vk = *(const float4*)&Kp[(size_t)(j0 + r) * DK + d4];
            sK[(d4 + 0) * SMEM_STRIDE + r] = vk.x;
            sK[(d4 + 1) * SMEM_STRIDE + r] = vk.y;
            sK[(d4 + 2) * SMEM_STRIDE + r] = vk.z;
            sK[(d4 + 3) * SMEM_STRIDE + r] = vk.w;
            float4 vv = *(const float4*)&Vp[(size_t)(j0 + r) * DK + d4];
            *(float4*)&sV[r * SMEM_STRIDE + d4] = vv;
        }
        __syncthreads();

        // S = Q K^T
        float sv[4][4];
#pragma unroll
        for (int i = 0; i < 4; i++)
#pragma unroll
            for (int j = 0; j < 4; j++) sv[i][j] = 0.f;
#pragma unroll 4
        for (int d = 0; d < 64; d++) {
            float4 q4 = *(float4*)&sQ[d * SMEM_STRIDE + r0];
            float4 k4 = *(float4*)&sK[d * SMEM_STRIDE + c0];
            float qa[4] = {q4.x, q4.y, q4.z, q4.w};
            float kb[4] = {k4.x, k4.y, k4.z, k4.w};
#pragma unroll
            for (int i = 0; i < 4; i++)
#pragma unroll
                for (int j = 0; j < 4; j++) sv[i][j] += qa[i] * kb[j];
        }

        const float scale = 0.125f;  // 1/sqrt(64)
        const bool diag = (jt == qt);

        // Register softmax with 16-lane shuffle reductions (tx-group = rows)
#pragma unroll
        for (int i = 0; i < 4; i++) {
            const int row = r0 + i;
            float mloc = -1e30f;
#pragma unroll
            for (int j = 0; j < 4; j++) {
                float s = sv[i][j] * scale;
                if (diag && (c0 + j) > row) s = -1e30f;
                sv[i][j] = s;
                mloc = fmaxf(mloc, s);
            }
#pragma unroll
            for (int o = 1; o < 16; o <<= 1)
                mloc = fmaxf(mloc, __shfl_xor_sync(0xffffffffu, mloc, o, 16));
            float mx = fmaxf(m_run[i], mloc);
            float cf = exp2f((m_run[i] - mx) * LOG2E);
            float rs = 0.f;
#pragma unroll
            for (int j = 0; j < 4; j++) {
                float p = exp2f((sv[i][j] - mx) * LOG2E);
                sv[i][j] = p;
                rs += p;
            }
#pragma unroll
            for (int o = 1; o < 16; o <<= 1)
                rs += __shfl_xor_sync(0xffffffffu, rs, o, 16);
            l_run[i] = l_run[i] * cf + rs;
            m_run[i] = mx;
#pragma unroll
            for (int j = 0; j < 4; j++) acc[i][j] *= cf;
        }

        // Write P transposed for the PV pass
#pragma unroll
        for (int i = 0; i < 4; i++)
#pragma unroll
            for (int j = 0; j < 4; j++)
                sS[(c0 + j) * SMEM_STRIDE + (r0 + i)] = sv[i][j];
        __syncthreads();

        // O += P V
#pragma unroll 4
        for (int jj = 0; jj < 64; jj++) {
            float4 p4 = *(float4*)&sS[jj * SMEM_STRIDE + r0];
            float4 v4 = *(float4*)&sV[jj * SMEM_STRIDE + c0];
            float pa[4] = {p4.x, p4.y, p4.z, p4.w};
            float vb[4] = {v4.x, v4.y, v4.z, v4.w};
#pragma unroll
            for (int i = 0; i < 4; i++)
#pragma unroll
                for (int j = 0; j < 4; j++) acc[i][j] += pa[i] * vb[j];
        }
    }

    // Epilogue: normalize, write context in [B,S,D] layout
    float inv[4];
#pragma unroll
    for (int i = 0; i < 4; i++) inv[i] = 1.f / l_run[i];

    const int b = bh >> 4;
    const int h = bh & 15;
    float* out = Out + ((size_t)b * S_LEN + q0 + r0) * D_MODEL + h * DK + c0;
#pragma unroll
    for (int i = 0; i < 4; i++) {
        float4 v = make_float4(acc[i][0] * inv[i], acc[i][1] * inv[i],
                               acc[i][2] * inv[i], acc[i][3] * inv[i]);
        *(float4*)&out[(size_t)i * D_MODEL] = v;
    }
}

// ---------------------------------------------------------------------------
extern "C" void kernel_launch(void* const* d_in, const int* in_sizes, int n_in,
                              void* d_out, int out_size)
{
    const float* x  = (const float*)d_in[0];
    const float* Wq = (const float*)d_in[1];
    const float* Wk = (const float*)d_in[2];
    const float* Wv = (const float*)d_in[3];
    const float* Wo = (const float*)d_in[4];
    float* out = (float*)d_out;

    float *pQ, *pK, *pV, *pC;
    cudaGetSymbolAddress((void**)&pQ, g_Q);
    cudaGetSymbolAddress((void**)&pK, g_K);
    cudaGetSymbolAddress((void**)&pV, g_V);
    cudaGetSymbolAddress((void**)&pC, g_C);

    const int attn_smem = (4 * 64 * SMEM_STRIDE) * sizeof(float);
    cudaFuncSetAttribute(attn_kernel, cudaFuncAttributeMaxDynamicSharedMemorySize,
                         attn_smem);

    dim3 qkvGrid(D_MODEL / 128, MTOT / 128, 3);   // (8, 32, 3)
    gemm_qkv<<<qkvGrid, 256>>>(x, Wq, Wk, Wv, pQ, pK, pV, MTOT, D_MODEL, D_MODEL);

    dim3 aGrid(S_LEN / 64, BATCH * NHEAD);        // (32, 32)
    attn_kernel<<<aGrid, 256, attn_smem>>>(pQ, pK, pV, pC);

    dim3 oGrid(D_MODEL / 128, MTOT / 128);        // (8, 32)
    gemm_out<<<oGrid, 256>>>(pC, Wo, out, MTOT, D_MODEL, D_MODEL);
}

// round 4
// speedup vs baseline: 2.4667x; 2.4281x over previous
#include <cuda_runtime.h>
#include <cuda_bf16.h>
#include <math.h>
#include <stdint.h>

#define S_LEN   2048
#define D_MODEL 1024
#define NHEAD   16
#define DK      64
#define BATCH   2
#define MTOT    (BATCH * S_LEN)      // 4096
#define MB      (1024*1024)
#define LOG2E   1.4426950408889634f

using bf = __nv_bfloat16;

// ---------------- scratch (bf16 hi/lo split representations) ----------------
__device__ bf g_Xhi[MTOT * D_MODEL],  g_Xlo[MTOT * D_MODEL];    // input x
__device__ bf g_Whi[4 * MB],          g_Wlo[4 * MB];            // Wq,Wk,Wv,Wo
__device__ bf g_Qhi[BATCH*NHEAD*S_LEN*DK], g_Qlo[BATCH*NHEAD*S_LEN*DK]; // [B,H,S,dk]
__device__ bf g_Khi[BATCH*NHEAD*S_LEN*DK], g_Klo[BATCH*NHEAD*S_LEN*DK]; // [B,H,S,dk]
__device__ bf g_VThi[BATCH*NHEAD*DK*S_LEN], g_VTlo[BATCH*NHEAD*DK*S_LEN]; // [B,H,dk,S]
__device__ bf g_Chi[MTOT * D_MODEL],  g_Clo[MTOT * D_MODEL];    // context [B,S,D]

// ---------------- helpers ----------------
__device__ __forceinline__ void mma_bf16(float* c, const uint32_t* a, const uint32_t* b) {
    asm volatile(
        "mma.sync.aligned.m16n8k16.row.col.f32.bf16.bf16.f32 "
        "{%0,%1,%2,%3}, {%4,%5,%6,%7}, {%8,%9}, {%0,%1,%2,%3};"
        : "+f"(c[0]), "+f"(c[1]), "+f"(c[2]), "+f"(c[3])
        : "r"(a[0]), "r"(a[1]), "r"(a[2]), "r"(a[3]), "r"(b[0]), "r"(b[1]));
}

__device__ __forceinline__ void cpa16(uint32_t dst, const void* src) {
    asm volatile("cp.async.cg.shared.global [%0], [%1], 16;" :: "r"(dst), "l"(src));
}
__device__ __forceinline__ void cp_commit() { asm volatile("cp.async.commit_group;"); }
template<int N> __device__ __forceinline__ void cp_wait() {
    asm volatile("cp.async.wait_group %0;" :: "n"(N)); }

__device__ __forceinline__ unsigned short bfbits(bf v) { return *(unsigned short*)&v; }

// split pair (x,y) into packed bf16x2 hi and lo words (elem0 = low half)
__device__ __forceinline__ void split2(float x, float y, uint32_t& hi, uint32_t& lo) {
    bf hx = __float2bfloat16_rn(x), hy = __float2bfloat16_rn(y);
    bf lx = __float2bfloat16_rn(x - __bfloat162float(hx));
    bf ly = __float2bfloat16_rn(y - __bfloat162float(hy));
    hi = (uint32_t)bfbits(hx) | ((uint32_t)bfbits(hy) << 16);
    lo = (uint32_t)bfbits(lx) | ((uint32_t)bfbits(ly) << 16);
}

// ---------------- pre-pass: fp32 -> bf16 hi/lo ----------------
__global__ void split_kernel(const float4* __restrict__ src,
                             uint2* __restrict__ hi, uint2* __restrict__ lo, int n4)
{
    int i = blockIdx.x * blockDim.x + threadIdx.x;
    for (; i < n4; i += gridDim.x * blockDim.x) {
        float4 v = src[i];
        uint32_t h0, l0, h1, l1;
        split2(v.x, v.y, h0, l0);
        split2(v.z, v.w, h1, l1);
        hi[i] = make_uint2(h0, h1);
        lo[i] = make_uint2(l0, l1);
    }
}

// ---------------- GEMM core: C = A[M,K] @ W[N,K]^T  (bf16x3 on tensor cores)
// 128x128x32 block tile, 256 threads, warp tile 64x32 (2x4 warp grid).
// smem layout per buffer (halves): Ahi[128][40] Alo Bhi Blo
// ----------------------------------------------------------------------------
#define GSA   40                       // smem half-stride
#define ARR   (128 * GSA)              // 5120 halves per array
#define BUFH  (4 * ARR)                // halves per buffer
#define GEMM_SMEM (2 * BUFH * 2)       // bytes = 81920

__device__ __forceinline__ void gemm_accum(
    const bf* __restrict__ Ahi, const bf* __restrict__ Alo,
    const bf* __restrict__ Bhi, const bf* __restrict__ Blo,
    int mBase, int nBase, bf* S, float c[4][4][4])
{
    const int tid = threadIdx.x;
    const int lane = tid & 31, w = tid >> 5;
    const int wm = w >> 2, wn = w & 3;           // warp grid 2x4
    const int g = lane >> 2, c2 = (lane & 3) * 2;
    const uint32_t sb = (uint32_t)__cvta_generic_to_shared(S);

    auto issue = [&](int stage, int buf) {
        const int kc = stage * 32;
#pragma unroll
        for (int i = 0; i < 2; i++) {
            int idx = tid + i * 256;             // 0..511
            int row = idx >> 2;                  // 0..127
            int k8  = (idx & 3) * 8;
            uint32_t db = sb + (uint32_t)(buf * BUFH + row * GSA + k8) * 2;
            cpa16(db,                 Ahi + (size_t)(mBase + row) * D_MODEL + kc + k8);
            cpa16(db + ARR * 2,       Alo + (size_t)(mBase + row) * D_MODEL + kc + k8);
            cpa16(db + 2 * ARR * 2,   Bhi + (size_t)(nBase + row) * D_MODEL + kc + k8);
            cpa16(db + 3 * ARR * 2,   Blo + (size_t)(nBase + row) * D_MODEL + kc + k8);
        }
        cp_commit();
    };

#pragma unroll
    for (int mi = 0; mi < 4; mi++)
#pragma unroll
        for (int ni = 0; ni < 4; ni++)
#pragma unroll
            for (int v = 0; v < 4; v++) c[mi][ni][v] = 0.f;

    issue(0, 0);
    int buf = 0;
    const int NSTAGE = D_MODEL / 32;             // 32

    for (int st = 0; st < NSTAGE; st++) {
        if (st + 1 < NSTAGE) { issue(st + 1, buf ^ 1); cp_wait<1>(); }
        else                 { cp_wait<0>(); }
        __syncthreads();

        const bf* sAhi = S + buf * BUFH;
        const bf* sAlo = sAhi + ARR;
        const bf* sBhi = sAhi + 2 * ARR;
        const bf* sBlo = sAhi + 3 * ARR;

#pragma unroll
        for (int ks = 0; ks < 2; ks++) {
            const int kb = ks * 16;
            uint32_t ahi[4][4], alo[4][4];
#pragma unroll
            for (int mi = 0; mi < 4; mi++) {
                int r = wm * 64 + mi * 16 + g;
                ahi[mi][0] = *(const uint32_t*)&sAhi[r * GSA + kb + c2];
                ahi[mi][1] = *(const uint32_t*)&sAhi[(r + 8) * GSA + kb + c2];
                ahi[mi][2] = *(const uint32_t*)&sAhi[r * GSA + kb + c2 + 8];
                ahi[mi][3] = *(const uint32_t*)&sAhi[(r + 8) * GSA + kb + c2 + 8];
                alo[mi][0] = *(const uint32_t*)&sAlo[r * GSA + kb + c2];
                alo[mi][1] = *(const uint32_t*)&sAlo[(r + 8) * GSA + kb + c2];
                alo[mi][2] = *(const uint32_t*)&sAlo[r * GSA + kb + c2 + 8];
                alo[mi][3] = *(const uint32_t*)&sAlo[(r + 8) * GSA + kb + c2 + 8];
            }
#pragma unroll
            for (int ni = 0; ni < 4; ni++) {
                int n = wn * 32 + ni * 8 + g;
                uint32_t bhi[2], blo[2];
                bhi[0] = *(const uint32_t*)&sBhi[n * GSA + kb + c2];
                bhi[1] = *(const uint32_t*)&sBhi[n * GSA + kb + c2 + 8];
                blo[0] = *(const uint32_t*)&sBlo[n * GSA + kb + c2];
                blo[1] = *(const uint32_t*)&sBlo[n * GSA + kb + c2 + 8];
#pragma unroll
                for (int mi = 0; mi < 4; mi++) {
                    mma_bf16(c[mi][ni], ahi[mi], bhi);
                    mma_bf16(c[mi][ni], ahi[mi], blo);
                    mma_bf16(c[mi][ni], alo[mi], bhi);
                }
            }
        }
        __syncthreads();
        buf ^= 1;
    }
}

// QKV projection. blockIdx.z: 0=Q, 1=K (both [B,H,S,dk] hi/lo), 2=V transposed [B,H,dk,S].
__global__ __launch_bounds__(256, 2)
void gemm_qkv_tc()
{
    extern __shared__ bf S[];
    float c[4][4][4];
    const int z = blockIdx.z;
    const int mBase = blockIdx.y * 128, nBase = blockIdx.x * 128;
    gemm_accum(g_Xhi, g_Xlo, g_Whi + (size_t)z * MB, g_Wlo + (size_t)z * MB,
               mBase, nBase, S, c);

    const int lane = threadIdx.x & 31, w = threadIdx.x >> 5;
    const int wm = w >> 2, wn = w & 3;
    const int g = lane >> 2, c2 = (lane & 3) * 2;

    bf* dsthi = (z == 0) ? g_Qhi : (z == 1) ? g_Khi : g_VThi;
    bf* dstlo = (z == 0) ? g_Qlo : (z == 1) ? g_Klo : g_VTlo;

#pragma unroll
    for (int mi = 0; mi < 4; mi++) {
#pragma unroll
        for (int ni = 0; ni < 4; ni++) {
            int m = mBase + wm * 64 + mi * 16 + g;
            int n = nBase + wn * 32 + ni * 8 + c2;
            int b = m >> 11, s = m & (S_LEN - 1);
            int h = n >> 6, d = n & 63;
            if (z < 2) {
                size_t o = (((size_t)(b * NHEAD + h)) * S_LEN + s) * DK + d;
                uint32_t hi, lo;
                split2(c[mi][ni][0], c[mi][ni][1], hi, lo);
                *(uint32_t*)&dsthi[o] = hi; *(uint32_t*)&dstlo[o] = lo;
                split2(c[mi][ni][2], c[mi][ni][3], hi, lo);
                *(uint32_t*)&dsthi[o + 8 * DK] = hi; *(uint32_t*)&dstlo[o + 8 * DK] = lo;
            } else {
                // transposed store: VT[b][h][d][s]
#pragma unroll
                for (int v = 0; v < 4; v++) {
                    int dd = d + (v & 1);
                    int ss = s + (v >> 1) * 8;
                    float val = c[mi][ni][v];
                    bf hv = __float2bfloat16_rn(val);
                    bf lv = __float2bfloat16_rn(val - __bfloat162float(hv));
                    size_t o = (((size_t)(b * NHEAD + h)) * DK + dd) * S_LEN + ss;
                    dsthi[o] = hv; dstlo[o] = lv;
                }
            }
        }
    }
}

// Output projection: context(bf16 hi/lo) @ Wo^T -> fp32 out [M,N]
__global__ __launch_bounds__(256, 2)
void gemm_out_tc(float* __restrict__ out)
{
    extern __shared__ bf S[];
    float c[4][4][4];
    const int mBase = blockIdx.y * 128, nBase = blockIdx.x * 128;
    gemm_accum(g_Chi, g_Clo, g_Whi + (size_t)3 * MB, g_Wlo + (size_t)3 * MB,
               mBase, nBase, S, c);

    const int lane = threadIdx.x & 31, w = threadIdx.x >> 5;
    const int wm = w >> 2, wn = w & 3;
    const int g = lane >> 2, c2 = (lane & 3) * 2;

#pragma unroll
    for (int mi = 0; mi < 4; mi++) {
#pragma unroll
        for (int ni = 0; ni < 4; ni++) {
            int m = mBase + wm * 64 + mi * 16 + g;
            int n = nBase + wn * 32 + ni * 8 + c2;
            *(float2*)&out[(size_t)m * D_MODEL + n] =
                make_float2(c[mi][ni][0], c[mi][ni][1]);
            *(float2*)&out[(size_t)(m + 8) * D_MODEL + n] =
                make_float2(c[mi][ni][2], c[mi][ni][3]);
        }
    }
}

// ---------------- Flash attention on tensor cores, causal --------------------
// Br=128, Bc=64, 256 threads, 8 warps; warp owns a 16-row strip (full rows ->
// warp-local softmax). bf16x3 for QK^T and PV. K/V loaded with cp.async.
// smem halves layout:
#define ASA 72                              // half stride
#define QH_OFF  0
#define QL_OFF  (128 * ASA)                 // 9216
#define KH_OFF  (2 * 128 * ASA)             // 18432
#define KL_OFF  (KH_OFF + 64 * ASA)
#define VH_OFF  (KL_OFF + 64 * ASA)
#define VL_OFF  (VH_OFF + 64 * ASA)
#define PH_OFF  (VL_OFF + 64 * ASA)         // 36864
#define PL_OFF  (PH_OFF + 128 * ASA)
#define ATTN_SMEM ((PL_OFF + 128 * ASA) * 2)  // 110592 bytes

__global__ __launch_bounds__(256, 2)
void attn_tc(float* __restrict__ dummy)
{
    extern __shared__ bf S[];
    const int tid = threadIdx.x;
    const int lane = tid & 31, w = tid >> 5;      // 8 warps, warp = 16 rows
    const int g = lane >> 2, c2 = (lane & 3) * 2;
    const int qt = (int)gridDim.x - 1 - (int)blockIdx.x;  // largest-first
    const int bh = blockIdx.y;
    const int q0 = qt * 128;
    const uint32_t sb = (uint32_t)__cvta_generic_to_shared(S);

    const bf* Qhi = g_Qhi + (size_t)bh * S_LEN * DK;
    const bf* Qlo = g_Qlo + (size_t)bh * S_LEN * DK;
    const bf* Khi = g_Khi + (size_t)bh * S_LEN * DK;
    const bf* Klo = g_Klo + (size_t)bh * S_LEN * DK;
    const bf* VThi = g_VThi + (size_t)bh * DK * S_LEN;
    const bf* VTlo = g_VTlo + (size_t)bh * DK * S_LEN;

    // issue Q tile loads (128 x 64 halves, hi+lo)
#pragma unroll
    for (int i = 0; i < 4; i++) {
        int idx = tid + i * 256;                  // 0..1023
        int row = idx >> 3, d8 = (idx & 7) * 8;
        uint32_t db = sb + (uint32_t)(row * ASA + d8) * 2;
        cpa16(db + QH_OFF * 2, Qhi + (size_t)(q0 + row) * DK + d8);
        cpa16(db + QL_OFF * 2, Qlo + (size_t)(q0 + row) * DK + d8);
    }
    cp_commit();

    float o_acc[8][4];
#pragma unroll
    for (int nt = 0; nt < 8; nt++)
#pragma unroll
        for (int v = 0; v < 4; v++) o_acc[nt][v] = 0.f;
    float m_a = -1e30f, m_b = -1e30f, l_a = 0.f, l_b = 0.f;

    const int growA = q0 + 16 * w + g;
    const int growB = growA + 8;
    const int jt_max = 2 * qt + 1;

    for (int jt = 0; jt <= jt_max; jt++) {
        const int j0 = jt * 64;
        __syncthreads();                           // prev iter done with sK/sVT
#pragma unroll
        for (int i = 0; i < 2; i++) {
            int idx = tid + i * 256;               // 0..511
            int row = idx >> 3, d8 = (idx & 7) * 8;
            uint32_t db = sb + (uint32_t)(row * ASA + d8) * 2;
            cpa16(db + KH_OFF * 2, Khi + (size_t)(j0 + row) * DK + d8);
            cpa16(db + KL_OFF * 2, Klo + (size_t)(j0 + row) * DK + d8);
            cpa16(db + VH_OFF * 2, VThi + (size_t)row * S_LEN + j0 + d8);
            cpa16(db + VL_OFF * 2, VTlo + (size_t)row * S_LEN + j0 + d8);
        }
        cp_commit();
        cp_wait<0>();
        __syncthreads();

        // ---- S = Q K^T ----
        float sc[8][4];
#pragma unroll
        for (int nt = 0; nt < 8; nt++)
#pragma unroll
            for (int v = 0; v < 4; v++) sc[nt][v] = 0.f;

#pragma unroll
        for (int ks = 0; ks < 4; ks++) {
            const int kb = ks * 16;
            const int rA = 16 * w + g;
            uint32_t ahi[4], alo[4];
            ahi[0] = *(const uint32_t*)&S[QH_OFF + rA * ASA + kb + c2];
            ahi[1] = *(const uint32_t*)&S[QH_OFF + (rA + 8) * ASA + kb + c2];
            ahi[2] = *(const uint32_t*)&S[QH_OFF + rA * ASA + kb + c2 + 8];
            ahi[3] = *(const uint32_t*)&S[QH_OFF + (rA + 8) * ASA + kb + c2 + 8];
            alo[0] = *(const uint32_t*)&S[QL_OFF + rA * ASA + kb + c2];
            alo[1] = *(const uint32_t*)&S[QL_OFF + (rA + 8) * ASA + kb + c2];
            alo[2] = *(const uint32_t*)&S[QL_OFF + rA * ASA + kb + c2 + 8];
            alo[3] = *(const uint32_t*)&S[QL_OFF + (rA + 8) * ASA + kb + c2 + 8];
#pragma unroll
            for (int nt = 0; nt < 8; nt++) {
                int n = nt * 8 + g;
                uint32_t bhi[2], blo[2];
                bhi[0] = *(const uint32_t*)&S[KH_OFF + n * ASA + kb + c2];
                bhi[1] = *(const uint32_t*)&S[KH_OFF + n * ASA + kb + c2 + 8];
                blo[0] = *(const uint32_t*)&S[KL_OFF + n * ASA + kb + c2];
                blo[1] = *(const uint32_t*)&S[KL_OFF + n * ASA + kb + c2 + 8];
                mma_bf16(sc[nt], ahi, bhi);
                mma_bf16(sc[nt], ahi, blo);
                mma_bf16(sc[nt], alo, bhi);
            }
        }

        // ---- softmax (warp-local, rows rA and rA+8) ----
        const bool diag = (jt >= 2 * qt);
        float mA = -1e30f, mB = -1e30f;
#pragma unroll
        for (int nt = 0; nt < 8; nt++) {
            int col = j0 + nt * 8 + c2;
#pragma unroll
            for (int v = 0; v < 4; v++) sc[nt][v] *= 0.125f;
            if (diag) {
                if (col     > growA) sc[nt][0] = -1e30f;
                if (col + 1 > growA) sc[nt][1] = -1e30f;
                if (col     > growB) sc[nt][2] = -1e30f;
                if (col + 1 > growB) sc[nt][3] = -1e30f;
            }
            mA = fmaxf(mA, fmaxf(sc[nt][0], sc[nt][1]));
            mB = fmaxf(mB, fmaxf(sc[nt][2], sc[nt][3]));
        }
#pragma unroll
        for (int o = 1; o < 4; o <<= 1) {
            mA = fmaxf(mA, __shfl_xor_sync(0xffffffffu, mA, o, 4));
            mB = fmaxf(mB, __shfl_xor_sync(0xffffffffu, mB, o, 4));
        }
        float mxA = fmaxf(m_a, mA), mxB = fmaxf(m_b, mB);
        float cfA = exp2f((m_a - mxA) * LOG2E);
        float cfB = exp2f((m_b - mxB) * LOG2E);
        float rsA = 0.f, rsB = 0.f;
        const int rA = 16 * w + g;
#pragma unroll
        for (int nt = 0; nt < 8; nt++) {
            float p0 = exp2f((sc[nt][0] - mxA) * LOG2E);
            float p1 = exp2f((sc[nt][1] - mxA) * LOG2E);
            float p2 = exp2f((sc[nt][2] - mxB) * LOG2E);
            float p3 = exp2f((sc[nt][3] - mxB) * LOG2E);
            rsA += p0 + p1; rsB += p2 + p3;
            uint32_t hi, lo;
            split2(p0, p1, hi, lo);
            *(uint32_t*)&S[PH_OFF + rA * ASA + nt * 8 + c2] = hi;
            *(uint32_t*)&S[PL_OFF + rA * ASA + nt * 8 + c2] = lo;
            split2(p2, p3, hi, lo);
            *(uint32_t*)&S[PH_OFF + (rA + 8) * ASA + nt * 8 + c2] = hi;
            *(uint32_t*)&S[PL_OFF + (rA + 8) * ASA + nt * 8 + c2] = lo;
        }
#pragma unroll
        for (int o = 1; o < 4; o <<= 1) {
            rsA += __shfl_xor_sync(0xffffffffu, rsA, o, 4);
            rsB += __shfl_xor_sync(0xffffffffu, rsB, o, 4);
        }
        l_a = l_a * cfA + rsA;  m_a = mxA;
        l_b = l_b * cfB + rsB;  m_b = mxB;
#pragma unroll
        for (int nt = 0; nt < 8; nt++) {
            o_acc[nt][0] *= cfA; o_acc[nt][1] *= cfA;
            o_acc[nt][2] *= cfB; o_acc[nt][3] *= cfB;
        }
        __syncwarp();

        // ---- O += P V  (A = P rows of this warp, B = VT) ----
#pragma unroll
        for (int ks = 0; ks < 4; ks++) {
            const int kb = ks * 16;
            uint32_t ahi[4], alo[4];
            ahi[0] = *(const uint32_t*)&S[PH_OFF + rA * ASA + kb + c2];
            ahi[1] = *(const uint32_t*)&S[PH_OFF + (rA + 8) * ASA + kb + c2];
            ahi[2] = *(const uint32_t*)&S[PH_OFF + rA * ASA + kb + c2 + 8];
            ahi[3] = *(const uint32_t*)&S[PH_OFF + (rA + 8) * ASA + kb + c2 + 8];
            alo[0] = *(const uint32_t*)&S[PL_OFF + rA * ASA + kb + c2];
            alo[1] = *(const uint32_t*)&S[PL_OFF + (rA + 8) * ASA + kb + c2];
            alo[2] = *(const uint32_t*)&S[PL_OFF + rA * ASA + kb + c2 + 8];
            alo[3] = *(const uint32_t*)&S[PL_OFF + (rA + 8) * ASA + kb + c2 + 8];
#pragma unroll
            for (int nt = 0; nt < 8; nt++) {
                int n = nt * 8 + g;
                uint32_t bhi[2], blo[2];
                bhi[0] = *(const uint32_t*)&S[VH_OFF + n * ASA + kb + c2];
                bhi[1] = *(const uint32_t*)&S[VH_OFF + n * ASA + kb + c2 + 8];
                blo[0] = *(const uint32_t*)&S[VL_OFF + n * ASA + kb + c2];
                blo[1] = *(const uint32_t*)&S[VL_OFF + n * ASA + kb + c2 + 8];
                mma_bf16(o_acc[nt], ahi, bhi);
                mma_bf16(o_acc[nt], ahi, blo);
                mma_bf16(o_acc[nt], alo, bhi);
            }
        }
    }

    // ---- epilogue: normalize, split to bf16 hi/lo context [B,S,D] ----
    const float invA = 1.f / l_a, invB = 1.f / l_b;
    const int b = bh >> 4, h = bh & 15;
    const int sA = q0 + 16 * w + g;
#pragma unroll
    for (int nt = 0; nt < 8; nt++) {
        int col = h * DK + nt * 8 + c2;
        uint32_t hi, lo;
        split2(o_acc[nt][0] * invA, o_acc[nt][1] * invA, hi, lo);
        size_t o = ((size_t)(b * S_LEN + sA)) * D_MODEL + col;
        *(uint32_t*)&g_Chi[o] = hi; *(uint32_t*)&g_Clo[o] = lo;
        split2(o_acc[nt][2] * invB, o_acc[nt][3] * invB, hi, lo);
        size_t o2 = ((size_t)(b * S_LEN + sA + 8)) * D_MODEL + col;
        *(uint32_t*)&g_Chi[o2] = hi; *(uint32_t*)&g_Clo[o2] = lo;
    }
}

// ---------------------------------------------------------------------------
extern "C" void kernel_launch(void* const* d_in, const int* in_sizes, int n_in,
                              void* d_out, int out_size)
{
    const float* x  = (const float*)d_in[0];
    const float* Wq = (const float*)d_in[1];
    const float* Wk = (const float*)d_in[2];
    const float* Wv = (const float*)d_in[3];
    const float* Wo = (const float*)d_in[4];
    float* out = (float*)d_out;

    bf *pXhi, *pXlo, *pWhi, *pWlo;
    cudaGetSymbolAddress((void**)&pXhi, g_Xhi);
    cudaGetSymbolAddress((void**)&pXlo, g_Xlo);
    cudaGetSymbolAddress((void**)&pWhi, g_Whi);
    cudaGetSymbolAddress((void**)&pWlo, g_Wlo);

    static bool configured = false;
    if (!configured) {
        cudaFuncSetAttribute(gemm_qkv_tc, cudaFuncAttributeMaxDynamicSharedMemorySize, GEMM_SMEM);
        cudaFuncSetAttribute(gemm_out_tc, cudaFuncAttributeMaxDynamicSharedMemorySize, GEMM_SMEM);
        cudaFuncSetAttribute(attn_tc, cudaFuncAttributeMaxDynamicSharedMemorySize, ATTN_SMEM);
        configured = true;
    }

    // pre-pass: split inputs into bf16 hi/lo
    split_kernel<<<2048, 256>>>((const float4*)x, (uint2*)pXhi, (uint2*)pXlo,
                                MTOT * D_MODEL / 4);
    split_kernel<<<1024, 256>>>((const float4*)Wq, (uint2*)(pWhi + 0 * (size_t)MB),
                                (uint2*)(pWlo + 0 * (size_t)MB), MB / 4);
    split_kernel<<<1024, 256>>>((const float4*)Wk, (uint2*)(pWhi + 1 * (size_t)MB),
                                (uint2*)(pWlo + 1 * (size_t)MB), MB / 4);
    split_kernel<<<1024, 256>>>((const float4*)Wv, (uint2*)(pWhi + 2 * (size_t)MB),
                                (uint2*)(pWlo + 2 * (size_t)MB), MB / 4);
    split_kernel<<<1024, 256>>>((const float4*)Wo, (uint2*)(pWhi + 3 * (size_t)MB),
                                (uint2*)(pWlo + 3 * (size_t)MB), MB / 4);

    dim3 qkvGrid(D_MODEL / 128, MTOT / 128, 3);
    gemm_qkv_tc<<<qkvGrid, 256, GEMM_SMEM>>>();

    dim3 aGrid(S_LEN / 128, BATCH * NHEAD);       // (16, 32)
    attn_tc<<<aGrid, 256, ATTN_SMEM>>>(out);

    dim3 oGrid(D_MODEL / 128, MTOT / 128);
    gemm_out_tc<<<oGrid, 256, GEMM_SMEM>>>(out);
}

// round 9
// speedup vs baseline: 2.5922x; 1.0509x over previous
#include <cuda_runtime.h>
#include <cuda_bf16.h>
#include <math.h>
#include <stdint.h>

#define S_LEN   2048
#define D_MODEL 1024
#define NHEAD   16
#define DK      64
#define BATCH   2
#define MTOT    (BATCH * S_LEN)      // 4096
#define MB      (1024*1024)
#define LOG2E   1.4426950408889634f

using bf = __nv_bfloat16;

// ---------------- scratch (bf16 hi/lo split representations) ----------------
__device__ bf g_Xhi[MTOT * D_MODEL],  g_Xlo[MTOT * D_MODEL];    // input x
__device__ bf g_Whi[4 * MB],          g_Wlo[4 * MB];            // Wq,Wk,Wv,Wo
__device__ bf g_Qhi[BATCH*NHEAD*S_LEN*DK], g_Qlo[BATCH*NHEAD*S_LEN*DK]; // [B,H,S,dk] (pre-scaled by 1/8)
__device__ bf g_Khi[BATCH*NHEAD*S_LEN*DK], g_Klo[BATCH*NHEAD*S_LEN*DK]; // [B,H,S,dk]
__device__ bf g_VThi[BATCH*NHEAD*DK*S_LEN], g_VTlo[BATCH*NHEAD*DK*S_LEN]; // [B,H,dk,S]
__device__ bf g_Chi[MTOT * D_MODEL],  g_Clo[MTOT * D_MODEL];    // context [B,S,D]

// ---------------- helpers ----------------
__device__ __forceinline__ void mma_bf16(float* c, const uint32_t* a, const uint32_t* b) {
    asm volatile(
        "mma.sync.aligned.m16n8k16.row.col.f32.bf16.bf16.f32 "
        "{%0,%1,%2,%3}, {%4,%5,%6,%7}, {%8,%9}, {%0,%1,%2,%3};"
        : "+f"(c[0]), "+f"(c[1]), "+f"(c[2]), "+f"(c[3])
        : "r"(a[0]), "r"(a[1]), "r"(a[2]), "r"(a[3]), "r"(b[0]), "r"(b[1]));
}

__device__ __forceinline__ void cpa16(uint32_t dst, const void* src) {
    asm volatile("cp.async.cg.shared.global [%0], [%1], 16;" :: "r"(dst), "l"(src));
}
__device__ __forceinline__ void cp_commit() { asm volatile("cp.async.commit_group;"); }
template<int N> __device__ __forceinline__ void cp_wait() {
    asm volatile("cp.async.wait_group %0;" :: "n"(N)); }

__device__ __forceinline__ unsigned short bfbits(bf v) { return *(unsigned short*)&v; }

// split pair (x,y) into packed bf16x2 hi and lo words (elem0 = low half)
__device__ __forceinline__ void split2(float x, float y, uint32_t& hi, uint32_t& lo) {
    bf hx = __float2bfloat16_rn(x), hy = __float2bfloat16_rn(y);
    bf lx = __float2bfloat16_rn(x - __bfloat162float(hx));
    bf ly = __float2bfloat16_rn(y - __bfloat162float(hy));
    hi = (uint32_t)bfbits(hx) | ((uint32_t)bfbits(hy) << 16);
    lo = (uint32_t)bfbits(lx) | ((uint32_t)bfbits(ly) << 16);
}

// ---------------- pre-pass: fp32 -> bf16 hi/lo ----------------
__global__ void split_kernel(const float4* __restrict__ src,
                             uint2* __restrict__ hi, uint2* __restrict__ lo, int n4)
{
    int i = blockIdx.x * blockDim.x + threadIdx.x;
    for (; i < n4; i += gridDim.x * blockDim.x) {
        float4 v = src[i];
        uint32_t h0, l0, h1, l1;
        split2(v.x, v.y, h0, l0);
        split2(v.z, v.w, h1, l1);
        hi[i] = make_uint2(h0, h1);
        lo[i] = make_uint2(l0, l1);
    }
}

// ---------------- GEMM core: C = A[M,K] @ W[N,K]^T  (bf16x3 on mma.sync) ----
// 128x128x32 block tile, 256 threads, warp tile 64x32 (2x4 warp grid).
#define GSA   40                       // smem half-stride
#define ARR   (128 * GSA)              // 5120 halves per array
#define BUFH  (4 * ARR)                // halves per buffer
#define GEMM_SMEM (2 * BUFH * 2)       // bytes = 81920

__device__ __forceinline__ void gemm_accum(
    const bf* __restrict__ Ahi, const bf* __restrict__ Alo,
    const bf* __restrict__ Bhi, const bf* __restrict__ Blo,
    int mBase, int nBase, bf* S, float c[4][4][4])
{
    const int tid = threadIdx.x;
    const int lane = tid & 31, w = tid >> 5;
    const int wm = w >> 2, wn = w & 3;           // warp grid 2x4
    const int g = lane >> 2, c2 = (lane & 3) * 2;
    const uint32_t sb = (uint32_t)__cvta_generic_to_shared(S);

    auto issue = [&](int stage, int buf) {
        const int kc = stage * 32;
#pragma unroll
        for (int i = 0; i < 2; i++) {
            int idx = tid + i * 256;             // 0..511
            int row = idx >> 2;                  // 0..127
            int k8  = (idx & 3) * 8;
            uint32_t db = sb + (uint32_t)(buf * BUFH + row * GSA + k8) * 2;
            cpa16(db,                 Ahi + (size_t)(mBase + row) * D_MODEL + kc + k8);
            cpa16(db + ARR * 2,       Alo + (size_t)(mBase + row) * D_MODEL + kc + k8);
            cpa16(db + 2 * ARR * 2,   Bhi + (size_t)(nBase + row) * D_MODEL + kc + k8);
            cpa16(db + 3 * ARR * 2,   Blo + (size_t)(nBase + row) * D_MODEL + kc + k8);
        }
        cp_commit();
    };

#pragma unroll
    for (int mi = 0; mi < 4; mi++)
#pragma unroll
        for (int ni = 0; ni < 4; ni++)
#pragma unroll
            for (int v = 0; v < 4; v++) c[mi][ni][v] = 0.f;

    issue(0, 0);
    int buf = 0;
    const int NSTAGE = D_MODEL / 32;             // 32

    for (int st = 0; st < NSTAGE; st++) {
        if (st + 1 < NSTAGE) { issue(st + 1, buf ^ 1); cp_wait<1>(); }
        else                 { cp_wait<0>(); }
        __syncthreads();

        const bf* sAhi = S + buf * BUFH;
        const bf* sAlo = sAhi + ARR;
        const bf* sBhi = sAhi + 2 * ARR;
        const bf* sBlo = sAhi + 3 * ARR;

#pragma unroll
        for (int ks = 0; ks < 2; ks++) {
            const int kb = ks * 16;
            uint32_t ahi[4][4], alo[4][4];
#pragma unroll
            for (int mi = 0; mi < 4; mi++) {
                int r = wm * 64 + mi * 16 + g;
                ahi[mi][0] = *(const uint32_t*)&sAhi[r * GSA + kb + c2];
                ahi[mi][1] = *(const uint32_t*)&sAhi[(r + 8) * GSA + kb + c2];
                ahi[mi][2] = *(const uint32_t*)&sAhi[r * GSA + kb + c2 + 8];
                ahi[mi][3] = *(const uint32_t*)&sAhi[(r + 8) * GSA + kb + c2 + 8];
                alo[mi][0] = *(const uint32_t*)&sAlo[r * GSA + kb + c2];
                alo[mi][1] = *(const uint32_t*)&sAlo[(r + 8) * GSA + kb + c2];
                alo[mi][2] = *(const uint32_t*)&sAlo[r * GSA + kb + c2 + 8];
                alo[mi][3] = *(const uint32_t*)&sAlo[(r + 8) * GSA + kb + c2 + 8];
            }
#pragma unroll
            for (int ni = 0; ni < 4; ni++) {
                int n = wn * 32 + ni * 8 + g;
                uint32_t bhi[2], blo[2];
                bhi[0] = *(const uint32_t*)&sBhi[n * GSA + kb + c2];
                bhi[1] = *(const uint32_t*)&sBhi[n * GSA + kb + c2 + 8];
                blo[0] = *(const uint32_t*)&sBlo[n * GSA + kb + c2];
                blo[1] = *(const uint32_t*)&sBlo[n * GSA + kb + c2 + 8];
#pragma unroll
                for (int mi = 0; mi < 4; mi++) {
                    mma_bf16(c[mi][ni], ahi[mi], bhi);
                    mma_bf16(c[mi][ni], ahi[mi], blo);
                    mma_bf16(c[mi][ni], alo[mi], bhi);
                }
            }
        }
        __syncthreads();
        buf ^= 1;
    }
}

// Fused Q/K/V projection: blockIdx.z selects weight/output. Q pre-scaled by 1/8.
__global__ __launch_bounds__(256, 2)
void gemm_qkv(const bf* __restrict__ Ahi, const bf* __restrict__ Alo,
              const bf* __restrict__ Whi, const bf* __restrict__ Wlo)
{
    extern __shared__ bf S[];
    float c[4][4][4];
    const int z = blockIdx.z;
    const int mBase = blockIdx.y * 128, nBase = blockIdx.x * 128;
    gemm_accum(Ahi, Alo, Whi + (size_t)z * MB, Wlo + (size_t)z * MB,
               mBase, nBase, S, c);

    const int lane = threadIdx.x & 31, w = threadIdx.x >> 5;
    const int wm = w >> 2, wn = w & 3;
    const int g = lane >> 2, c2 = (lane & 3) * 2;

    bf* dsthi = (z == 0) ? g_Qhi : (z == 1) ? g_Khi : g_VThi;
    bf* dstlo = (z == 0) ? g_Qlo : (z == 1) ? g_Klo : g_VTlo;
    const float qs = (z == 0) ? 0.125f : 1.0f;   // fold 1/sqrt(dk) into Q

#pragma unroll
    for (int mi = 0; mi < 4; mi++) {
#pragma unroll
        for (int ni = 0; ni < 4; ni++) {
            int m = mBase + wm * 64 + mi * 16 + g;
            int n = nBase + wn * 32 + ni * 8 + c2;
            int b = m >> 11, s = m & (S_LEN - 1);
            int h = n >> 6, d = n & 63;
            if (z < 2) {
                size_t o = (((size_t)(b * NHEAD + h)) * S_LEN + s) * DK + d;
                uint32_t hi, lo;
                split2(c[mi][ni][0] * qs, c[mi][ni][1] * qs, hi, lo);
                *(uint32_t*)&dsthi[o] = hi; *(uint32_t*)&dstlo[o] = lo;
                split2(c[mi][ni][2] * qs, c[mi][ni][3] * qs, hi, lo);
                *(uint32_t*)&dsthi[o + 8 * DK] = hi; *(uint32_t*)&dstlo[o + 8 * DK] = lo;
            } else {
                // transposed store: VT[b][h][d][s]
#pragma unroll
                for (int v = 0; v < 4; v++) {
                    int dd = d + (v & 1);
                    int ss = s + (v >> 1) * 8;
                    float val = c[mi][ni][v];
                    bf hv = __float2bfloat16_rn(val);
                    bf lv = __float2bfloat16_rn(val - __bfloat162float(hv));
                    size_t o = (((size_t)(b * NHEAD + h)) * DK + dd) * S_LEN + ss;
                    dsthi[o] = hv; dstlo[o] = lv;
                }
            }
        }
    }
}

// Output projection: context(bf16 hi/lo) @ Wo^T -> fp32 out [M,N]
__global__ __launch_bounds__(256, 2)
void gemm_out(const bf* __restrict__ Whi, const bf* __restrict__ Wlo,
              float* __restrict__ out)
{
    extern __shared__ bf S[];
    float c[4][4][4];
    const int mBase = blockIdx.y * 128, nBase = blockIdx.x * 128;
    gemm_accum(g_Chi, g_Clo, Whi + (size_t)3 * MB, Wlo + (size_t)3 * MB,
               mBase, nBase, S, c);

    const int lane = threadIdx.x & 31, w = threadIdx.x >> 5;
    const int wm = w >> 2, wn = w & 3;
    const int g = lane >> 2, c2 = (lane & 3) * 2;

#pragma unroll
    for (int mi = 0; mi < 4; mi++) {
#pragma unroll
        for (int ni = 0; ni < 4; ni++) {
            int m = mBase + wm * 64 + mi * 16 + g;
            int n = nBase + wn * 32 + ni * 8 + c2;
            *(float2*)&out[(size_t)m * D_MODEL + n] =
                make_float2(c[mi][ni][0], c[mi][ni][1]);
            *(float2*)&out[(size_t)(m + 8) * D_MODEL + n] =
                make_float2(c[mi][ni][2], c[mi][ni][3]);
        }
    }
}

// ---------------- Flash attention (mma.sync), causal -------------------------
// Br=128, Bc=64, 256 threads, 8 warps; warp owns a 16-row strip.
// P kept in registers (S-accumulator fragments == A-operand fragments).
// K/V double-buffered cp.async pipeline (prefetch jt+2 during compute of jt).
#define ASA 72                                // half stride
#define QH_OFF  0
#define QL_OFF  (128 * ASA)                   // 9216
#define ST_OFF  (2 * 128 * ASA)               // 18432
#define ST_SZ   (4 * 64 * ASA)                // 18432 halves per stage
#define ATTN_SMEM ((ST_OFF + 2 * ST_SZ) * 2)  // 110592 bytes

__global__ __launch_bounds__(256, 2)
void attn_tc(const bf* __restrict__ Qhi_g, const bf* __restrict__ Qlo_g,
             const bf* __restrict__ Khi_g, const bf* __restrict__ Klo_g,
             const bf* __restrict__ VThi_g, const bf* __restrict__ VTlo_g)
{
    extern __shared__ bf S[];
    const int tid = threadIdx.x;
    const int lane = tid & 31, w = tid >> 5;
    const int g = lane >> 2, c2 = (lane & 3) * 2;
    const int qt = (int)gridDim.x - 1 - (int)blockIdx.x;   // largest-first
    const int bh = blockIdx.y;
    const int q0 = qt * 128;
    const uint32_t sb = (uint32_t)__cvta_generic_to_shared(S);

    const bf* Qhi = Qhi_g + (size_t)bh * S_LEN * DK;
    const bf* Qlo = Qlo_g + (size_t)bh * S_LEN * DK;
    const bf* Khi = Khi_g + (size_t)bh * S_LEN * DK;
    const bf* Klo = Klo_g + (size_t)bh * S_LEN * DK;
    const bf* VThi = VThi_g + (size_t)bh * DK * S_LEN;
    const bf* VTlo = VTlo_g + (size_t)bh * DK * S_LEN;

    auto issueKV = [&](int jt, int stage) {
        const int j0 = jt * 64;
        const uint32_t base = sb + (uint32_t)(ST_OFF + stage * ST_SZ) * 2;
#pragma unroll
        for (int i = 0; i < 2; i++) {
            int idx = tid + i * 256;              // 0..511
            int row = idx >> 3, d8 = (idx & 7) * 8;
            uint32_t db = base + (uint32_t)(row * ASA + d8) * 2;
            cpa16(db,                    Khi + (size_t)(j0 + row) * DK + d8);
            cpa16(db + 4608 * 2,         Klo + (size_t)(j0 + row) * DK + d8);
            cpa16(db + 9216 * 2,         VThi + (size_t)row * S_LEN + j0 + d8);
            cpa16(db + 13824 * 2,        VTlo + (size_t)row * S_LEN + j0 + d8);
        }
        cp_commit();
    };

    // group 0: Q tile (128 x 64 halves, hi+lo)
#pragma unroll
    for (int i = 0; i < 4; i++) {
        int idx = tid + i * 256;                  // 0..1023
        int row = idx >> 3, d8 = (idx & 7) * 8;
        uint32_t db = sb + (uint32_t)(row * ASA + d8) * 2;
        cpa16(db + QH_OFF * 2, Qhi + (size_t)(q0 + row) * DK + d8);
        cpa16(db + QL_OFF * 2, Qlo + (size_t)(q0 + row) * DK + d8);
    }
    cp_commit();

    const int jt_max = 2 * qt + 1;
    issueKV(0, 0);
    if (jt_max >= 1) issueKV(1, 1);

    float o_acc[8][4];
#pragma unroll
    for (int nt = 0; nt < 8; nt++)
#pragma unroll
        for (int v = 0; v < 4; v++) o_acc[nt][v] = 0.f;
    float m_a = -1e30f, m_b = -1e30f, l_a = 0.f, l_b = 0.f;

    const int growA = q0 + 16 * w + g;
    const int growB = growA + 8;
    const int rA = 16 * w + g;

    for (int jt = 0; jt <= jt_max; jt++) {
        const int j0 = jt * 64;
        const int stage = jt & 1;
        const int KH = ST_OFF + stage * ST_SZ;
        const int KL = KH + 4608;
        const int VH = KH + 9216;
        const int VL = KH + 13824;

        if (jt == jt_max) cp_wait<0>(); else cp_wait<1>();
        __syncthreads();

        // ---- S = Q K^T (Q pre-scaled by 1/8) ----
        float sc[8][4];
#pragma unroll
        for (int nt = 0; nt < 8; nt++)
#pragma unroll
            for (int v = 0; v < 4; v++) sc[nt][v] = 0.f;

#pragma unroll
        for (int ks = 0; ks < 4; ks++) {
            const int kb = ks * 16;
            uint32_t ahi[4], alo[4];
            ahi[0] = *(const uint32_t*)&S[QH_OFF + rA * ASA + kb + c2];
            ahi[1] = *(const uint32_t*)&S[QH_OFF + (rA + 8) * ASA + kb + c2];
            ahi[2] = *(const uint32_t*)&S[QH_OFF + rA * ASA + kb + c2 + 8];
            ahi[3] = *(const uint32_t*)&S[QH_OFF + (rA + 8) * ASA + kb + c2 + 8];
            alo[0] = *(const uint32_t*)&S[QL_OFF + rA * ASA + kb + c2];
            alo[1] = *(const uint32_t*)&S[QL_OFF + (rA + 8) * ASA + kb + c2];
            alo[2] = *(const uint32_t*)&S[QL_OFF + rA * ASA + kb + c2 + 8];
            alo[3] = *(const uint32_t*)&S[QL_OFF + (rA + 8) * ASA + kb + c2 + 8];
#pragma unroll
            for (int nt = 0; nt < 8; nt++) {
                int n = nt * 8 + g;
                uint32_t bhi[2], blo[2];
                bhi[0] = *(const uint32_t*)&S[KH + n * ASA + kb + c2];
                bhi[1] = *(const uint32_t*)&S[KH + n * ASA + kb + c2 + 8];
                blo[0] = *(const uint32_t*)&S[KL + n * ASA + kb + c2];
                blo[1] = *(const uint32_t*)&S[KL + n * ASA + kb + c2 + 8];
                mma_bf16(sc[nt], ahi, bhi);
                mma_bf16(sc[nt], ahi, blo);
                mma_bf16(sc[nt], alo, bhi);
            }
        }

        // ---- softmax (warp-local) + pack P into A-operand registers ----
        const bool diag = (jt >= 2 * qt);
        float mA = -1e30f, mB = -1e30f;
#pragma unroll
        for (int nt = 0; nt < 8; nt++) {
            int col = j0 + nt * 8 + c2;
            if (diag) {
                if (col     > growA) sc[nt][0] = -1e30f;
                if (col + 1 > growA) sc[nt][1] = -1e30f;
                if (col     > growB) sc[nt][2] = -1e30f;
                if (col + 1 > growB) sc[nt][3] = -1e30f;
            }
            mA = fmaxf(mA, fmaxf(sc[nt][0], sc[nt][1]));
            mB = fmaxf(mB, fmaxf(sc[nt][2], sc[nt][3]));
        }
#pragma unroll
        for (int o = 1; o < 4; o <<= 1) {
            mA = fmaxf(mA, __shfl_xor_sync(0xffffffffu, mA, o, 4));
            mB = fmaxf(mB, __shfl_xor_sync(0xffffffffu, mB, o, 4));
        }
        float mxA = fmaxf(m_a, mA), mxB = fmaxf(m_b, mB);
        float cfA = exp2f((m_a - mxA) * LOG2E);
        float cfB = exp2f((m_b - mxB) * LOG2E);
        float rsA = 0.f, rsB = 0.f;
        uint32_t pa_hi[8], pa_lo[8], pb_hi[8], pb_lo[8];  // rows g / g+8
#pragma unroll
        for (int nt = 0; nt < 8; nt++) {
            float p0 = exp2f((sc[nt][0] - mxA) * LOG2E);
            float p1 = exp2f((sc[nt][1] - mxA) * LOG2E);
            float p2 = exp2f((sc[nt][2] - mxB) * LOG2E);
            float p3 = exp2f((sc[nt][3] - mxB) * LOG2E);
            rsA += p0 + p1; rsB += p2 + p3;
            split2(p0, p1, pa_hi[nt], pa_lo[nt]);
            split2(p2, p3, pb_hi[nt], pb_lo[nt]);
        }
#pragma unroll
        for (int o = 1; o < 4; o <<= 1) {
            rsA += __shfl_xor_sync(0xffffffffu, rsA, o, 4);
            rsB += __shfl_xor_sync(0xffffffffu, rsB, o, 4);
        }
        l_a = l_a * cfA + rsA;  m_a = mxA;
        l_b = l_b * cfB + rsB;  m_b = mxB;
#pragma unroll
        for (int nt = 0; nt < 8; nt++) {
            o_acc[nt][0] *= cfA; o_acc[nt][1] *= cfA;
            o_acc[nt][2] *= cfB; o_acc[nt][3] *= cfB;
        }

        // ---- O += P V  (P from registers, V^T from smem) ----
#pragma unroll
        for (int ks = 0; ks < 4; ks++) {
            const int kb = ks * 16;
            uint32_t ahi[4] = {pa_hi[2*ks], pb_hi[2*ks], pa_hi[2*ks+1], pb_hi[2*ks+1]};
            uint32_t alo[4] = {pa_lo[2*ks], pb_lo[2*ks], pa_lo[2*ks+1], pb_lo[2*ks+1]};
#pragma unroll
            for (int nt = 0; nt < 8; nt++) {
                int n = nt * 8 + g;
                uint32_t bhi[2], blo[2];
                bhi[0] = *(const uint32_t*)&S[VH + n * ASA + kb + c2];
                bhi[1] = *(const uint32_t*)&S[VH + n * ASA + kb + c2 + 8];
                blo[0] = *(const uint32_t*)&S[VL + n * ASA + kb + c2];
                blo[1] = *(const uint32_t*)&S[VL + n * ASA + kb + c2 + 8];
                mma_bf16(o_acc[nt], ahi, bhi);
                mma_bf16(o_acc[nt], ahi, blo);
                mma_bf16(o_acc[nt], alo, bhi);
            }
        }

        __syncthreads();                          // all warps done with this stage
        if (jt + 2 <= jt_max) issueKV(jt + 2, stage);
    }

    // ---- epilogue: normalize, split to bf16 hi/lo context [B,S,D] ----
    const float invA = 1.f / l_a, invB = 1.f / l_b;
    const int b = bh >> 4, h = bh & 15;
    const int sA = q0 + 16 * w + g;
#pragma unroll
    for (int nt = 0; nt < 8; nt++) {
        int col = h * DK + nt * 8 + c2;
        uint32_t hi, lo;
        split2(o_acc[nt][0] * invA, o_acc[nt][1] * invA, hi, lo);
        size_t o = ((size_t)(b * S_LEN + sA)) * D_MODEL + col;
        *(uint32_t*)&g_Chi[o] = hi; *(uint32_t*)&g_Clo[o] = lo;
        split2(o_acc[nt][2] * invB, o_acc[nt][3] * invB, hi, lo);
        size_t o2 = ((size_t)(b * S_LEN + sA + 8)) * D_MODEL + col;
        *(uint32_t*)&g_Chi[o2] = hi; *(uint32_t*)&g_Clo[o2] = lo;
    }
}

// ---------------------------------------------------------------------------
extern "C" void kernel_launch(void* const* d_in, const int* in_sizes, int n_in,
                              void* d_out, int out_size)
{
    const float* x  = (const float*)d_in[0];
    const float* Wq = (const float*)d_in[1];
    const float* Wk = (const float*)d_in[2];
    const float* Wv = (const float*)d_in[3];
    const float* Wo = (const float*)d_in[4];
    float* out = (float*)d_out;

    bf *pXhi, *pXlo, *pWhi, *pWlo;
    bf *pQhi, *pQlo, *pKhi, *pKlo, *pVThi, *pVTlo;
    cudaGetSymbolAddress((void**)&pXhi, g_Xhi);
    cudaGetSymbolAddress((void**)&pXlo, g_Xlo);
    cudaGetSymbolAddress((void**)&pWhi, g_Whi);
    cudaGetSymbolAddress((void**)&pWlo, g_Wlo);
    cudaGetSymbolAddress((void**)&pQhi, g_Qhi);
    cudaGetSymbolAddress((void**)&pQlo, g_Qlo);
    cudaGetSymbolAddress((void**)&pKhi, g_Khi);
    cudaGetSymbolAddress((void**)&pKlo, g_Klo);
    cudaGetSymbolAddress((void**)&pVThi, g_VThi);
    cudaGetSymbolAddress((void**)&pVTlo, g_VTlo);

    static bool configured = false;
    if (!configured) {
        cudaFuncSetAttribute(gemm_qkv, cudaFuncAttributeMaxDynamicSharedMemorySize, GEMM_SMEM);
        cudaFuncSetAttribute(gemm_out, cudaFuncAttributeMaxDynamicSharedMemorySize, GEMM_SMEM);
        cudaFuncSetAttribute(attn_tc,  cudaFuncAttributeMaxDynamicSharedMemorySize, ATTN_SMEM);
        configured = true;
    }

    // pre-pass: split inputs into bf16 hi/lo
    split_kernel<<<2048, 256>>>((const float4*)x, (uint2*)pXhi, (uint2*)pXlo,
                                MTOT * D_MODEL / 4);
    split_kernel<<<1024, 256>>>((const float4*)Wq, (uint2*)(pWhi + 0 * (size_t)MB),
                                (uint2*)(pWlo + 0 * (size_t)MB), MB / 4);
    split_kernel<<<1024, 256>>>((const float4*)Wk, (uint2*)(pWhi + 1 * (size_t)MB),
                                (uint2*)(pWlo + 1 * (size_t)MB), MB / 4);
    split_kernel<<<1024, 256>>>((const float4*)Wv, (uint2*)(pWhi + 2 * (size_t)MB),
                                (uint2*)(pWlo + 2 * (size_t)MB), MB / 4);
    split_kernel<<<1024, 256>>>((const float4*)Wo, (uint2*)(pWhi + 3 * (size_t)MB),
                                (uint2*)(pWlo + 3 * (size_t)MB), MB / 4);

    dim3 qkvGrid(D_MODEL / 128, MTOT / 128, 3);   // (8, 32, 3)
    gemm_qkv<<<qkvGrid, 256, GEMM_SMEM>>>(pXhi, pXlo, pWhi, pWlo);

    dim3 aGrid(S_LEN / 128, BATCH * NHEAD);       // (16, 32)
    attn_tc<<<aGrid, 256, ATTN_SMEM>>>(pQhi, pQlo, pKhi, pKlo, pVThi, pVTlo);

    dim3 oGrid(D_MODEL / 128, MTOT / 128);        // (8, 32)
    gemm_out<<<oGrid, 256, GEMM_SMEM>>>(pWhi, pWlo, out);
}

// round 11
// speedup vs baseline: 2.8160x; 1.0863x over previous
#include <cuda_runtime.h>
#include <cuda_bf16.h>
#include <math.h>
#include <stdint.h>

#define S_LEN   2048
#define D_MODEL 1024
#define NHEAD   16
#define DK      64
#define BATCH   2
#define MTOT    (BATCH * S_LEN)      // 4096
#define MB      (1024*1024)
#define LOG2E   1.4426950408889634f

using bf = __nv_bfloat16;

// ---------------- scratch (bf16 hi/lo split representations) ----------------
__device__ bf g_Xhi[MTOT * D_MODEL],  g_Xlo[MTOT * D_MODEL];    // input x
__device__ bf g_Whi[4 * MB],          g_Wlo[4 * MB];            // Wq,Wk,Wv,Wo
__device__ bf g_Qhi[BATCH*NHEAD*S_LEN*DK], g_Qlo[BATCH*NHEAD*S_LEN*DK]; // [B,H,S,dk] (pre-scaled by 1/8)
__device__ bf g_Khi[BATCH*NHEAD*S_LEN*DK], g_Klo[BATCH*NHEAD*S_LEN*DK]; // [B,H,S,dk]
__device__ bf g_VThi[BATCH*NHEAD*DK*S_LEN], g_VTlo[BATCH*NHEAD*DK*S_LEN]; // [B,H,dk,S]
__device__ bf g_Chi[MTOT * D_MODEL],  g_Clo[MTOT * D_MODEL];    // context [B,S,D]

// ---------------- helpers ----------------
__device__ __forceinline__ void mma_bf16(float* c, const uint32_t* a, const uint32_t* b) {
    asm volatile(
        "mma.sync.aligned.m16n8k16.row.col.f32.bf16.bf16.f32 "
        "{%0,%1,%2,%3}, {%4,%5,%6,%7}, {%8,%9}, {%0,%1,%2,%3};"
        : "+f"(c[0]), "+f"(c[1]), "+f"(c[2]), "+f"(c[3])
        : "r"(a[0]), "r"(a[1]), "r"(a[2]), "r"(a[3]), "r"(b[0]), "r"(b[1]));
}

// ldmatrix x4: four 8x8 b16 matrices; per-lane row address in saddr.
__device__ __forceinline__ void ldsm4(uint32_t* r, uint32_t saddr) {
    asm volatile("ldmatrix.sync.aligned.m8n8.x4.shared.b16 {%0,%1,%2,%3}, [%4];"
                 : "=r"(r[0]), "=r"(r[1]), "=r"(r[2]), "=r"(r[3]) : "r"(saddr));
}

__device__ __forceinline__ void cpa16(uint32_t dst, const void* src) {
    asm volatile("cp.async.cg.shared.global [%0], [%1], 16;" :: "r"(dst), "l"(src));
}
__device__ __forceinline__ void cp_commit() { asm volatile("cp.async.commit_group;"); }
template<int N> __device__ __forceinline__ void cp_wait() {
    asm volatile("cp.async.wait_group %0;" :: "n"(N)); }

__device__ __forceinline__ unsigned short bfbits(bf v) { return *(unsigned short*)&v; }

// split pair (x,y) into packed bf16x2 hi and lo words (elem0 = low half)
__device__ __forceinline__ void split2(float x, float y, uint32_t& hi, uint32_t& lo) {
    bf hx = __float2bfloat16_rn(x), hy = __float2bfloat16_rn(y);
    bf lx = __float2bfloat16_rn(x - __bfloat162float(hx));
    bf ly = __float2bfloat16_rn(y - __bfloat162float(hy));
    hi = (uint32_t)bfbits(hx) | ((uint32_t)bfbits(hy) << 16);
    lo = (uint32_t)bfbits(lx) | ((uint32_t)bfbits(ly) << 16);
}

// ---------------- pre-pass: fp32 -> bf16 hi/lo, all 5 tensors in one launch --
__global__ void split_all(const float4* __restrict__ x,  const float4* __restrict__ wq,
                          const float4* __restrict__ wk, const float4* __restrict__ wv,
                          const float4* __restrict__ wo,
                          uint2* __restrict__ xhi, uint2* __restrict__ xlo,
                          uint2* __restrict__ whi, uint2* __restrict__ wlo)
{
    const int NX = MTOT * D_MODEL / 4;       // 1048576 float4
    const int NW = MB / 4;                   // 262144 float4 per W
    const int total = NX + 4 * NW;
    for (int i = blockIdx.x * blockDim.x + threadIdx.x; i < total;
         i += gridDim.x * blockDim.x) {
        const float4* src; uint2 *dhi, *dlo; int j;
        if (i < NX) { src = x; dhi = xhi; dlo = xlo; j = i; }
        else {
            int k = i - NX; int z = k / NW; j = k - z * NW;
            src = (z == 0) ? wq : (z == 1) ? wk : (z == 2) ? wv : wo;
            dhi = whi + (size_t)z * NW; dlo = wlo + (size_t)z * NW;
        }
        float4 v = src[j];
        uint32_t h0, l0, h1, l1;
        split2(v.x, v.y, h0, l0);
        split2(v.z, v.w, h1, l1);
        dhi[j] = make_uint2(h0, h1);
        dlo[j] = make_uint2(l0, l1);
    }
}

// ---------------- GEMM core: C = A[M,K] @ W[N,K]^T  (bf16x3 on mma.sync) ----
// 128x128x32 block tile, 256 threads, warp tile 64x32 (2x4 warp grid).
#define GSA   40                       // smem half-stride
#define ARR   (128 * GSA)              // 5120 halves per array
#define BUFH  (4 * ARR)                // halves per buffer
#define GEMM_SMEM (2 * BUFH * 2)       // bytes = 81920

__device__ __forceinline__ void gemm_accum(
    const bf* __restrict__ Ahi, const bf* __restrict__ Alo,
    const bf* __restrict__ Bhi, const bf* __restrict__ Blo,
    int mBase, int nBase, bf* S, float c[4][4][4])
{
    const int tid = threadIdx.x;
    const int lane = tid & 31, w = tid >> 5;
    const int wm = w >> 2, wn = w & 3;           // warp grid 2x4
    const uint32_t sb = (uint32_t)__cvta_generic_to_shared(S);

    // ldmatrix lane-derived offsets
    const int a_r = lane & 15;                   // row in 16-row A tile
    const int a_c = (lane >> 4) * 8;             // k block 0/8
    const int b_r = ((lane >> 4) << 3) + (lane & 7);  // n row across 2 8-tiles
    const int b_c = ((lane >> 3) & 1) * 8;            // k block 0/8

    auto issue = [&](int stage, int buf) {
        const int kc = stage * 32;
#pragma unroll
        for (int i = 0; i < 2; i++) {
            int idx = tid + i * 256;             // 0..511
            int row = idx >> 2;                  // 0..127
            int k8  = (idx & 3) * 8;
            uint32_t db = sb + (uint32_t)(buf * BUFH + row * GSA + k8) * 2;
            cpa16(db,                 Ahi + (size_t)(mBase + row) * D_MODEL + kc + k8);
            cpa16(db + ARR * 2,       Alo + (size_t)(mBase + row) * D_MODEL + kc + k8);
            cpa16(db + 2 * ARR * 2,   Bhi + (size_t)(nBase + row) * D_MODEL + kc + k8);
            cpa16(db + 3 * ARR * 2,   Blo + (size_t)(nBase + row) * D_MODEL + kc + k8);
        }
        cp_commit();
    };

#pragma unroll
    for (int mi = 0; mi < 4; mi++)
#pragma unroll
        for (int ni = 0; ni < 4; ni++)
#pragma unroll
            for (int v = 0; v < 4; v++) c[mi][ni][v] = 0.f;

    issue(0, 0);
    int buf = 0;
    const int NSTAGE = D_MODEL / 32;             // 32

    for (int st = 0; st < NSTAGE; st++) {
        if (st + 1 < NSTAGE) { issue(st + 1, buf ^ 1); cp_wait<1>(); }
        else                 { cp_wait<0>(); }
        __syncthreads();

        const uint32_t aA = sb + (uint32_t)(buf * BUFH) * 2;   // A-hi base (bytes)
        const uint32_t aB = aA + 2 * ARR * 2;                  // B-hi base

#pragma unroll
        for (int ks = 0; ks < 2; ks++) {
            const int kb = ks * 16;
            uint32_t ahi[4][4], alo[4][4];
#pragma unroll
            for (int mi = 0; mi < 4; mi++) {
                uint32_t ar = aA + (uint32_t)((wm * 64 + mi * 16 + a_r) * GSA + kb + a_c) * 2;
                ldsm4(ahi[mi], ar);
                ldsm4(alo[mi], ar + ARR * 2);
            }
#pragma unroll
            for (int np = 0; np < 2; np++) {     // n-tile pairs (0,1) and (2,3)
                uint32_t br = aB + (uint32_t)((wn * 32 + np * 16 + b_r) * GSA + kb + b_c) * 2;
                uint32_t bhi[4], blo[4];
                ldsm4(bhi, br);
                ldsm4(blo, br + ARR * 2);
#pragma unroll
                for (int q = 0; q < 2; q++) {
                    const int ni = np * 2 + q;
#pragma unroll
                    for (int mi = 0; mi < 4; mi++) {
                        mma_bf16(c[mi][ni], ahi[mi], bhi + q * 2);
                        mma_bf16(c[mi][ni], ahi[mi], blo + q * 2);
                        mma_bf16(c[mi][ni], alo[mi], bhi + q * 2);
                    }
                }
            }
        }
        __syncthreads();
        buf ^= 1;
    }
}

// Fused Q/K/V projection: blockIdx.z selects weight/output. Q pre-scaled by 1/8.
__global__ __launch_bounds__(256, 2)
void gemm_qkv(const bf* __restrict__ Ahi, const bf* __restrict__ Alo,
              const bf* __restrict__ Whi, const bf* __restrict__ Wlo)
{
    extern __shared__ bf S[];
    float c[4][4][4];
    const int z = blockIdx.z;
    const int mBase = blockIdx.y * 128, nBase = blockIdx.x * 128;
    gemm_accum(Ahi, Alo, Whi + (size_t)z * MB, Wlo + (size_t)z * MB,
               mBase, nBase, S, c);

    const int lane = threadIdx.x & 31, w = threadIdx.x >> 5;
    const int wm = w >> 2, wn = w & 3;
    const int g = lane >> 2, c2 = (lane & 3) * 2;

    bf* dsthi = (z == 0) ? g_Qhi : (z == 1) ? g_Khi : g_VThi;
    bf* dstlo = (z == 0) ? g_Qlo : (z == 1) ? g_Klo : g_VTlo;
    const float qs = (z == 0) ? 0.125f : 1.0f;   // fold 1/sqrt(dk) into Q

#pragma unroll
    for (int mi = 0; mi < 4; mi++) {
#pragma unroll
        for (int ni = 0; ni < 4; ni++) {
            int m = mBase + wm * 64 + mi * 16 + g;
            int n = nBase + wn * 32 + ni * 8 + c2;
            int b = m >> 11, s = m & (S_LEN - 1);
            int h = n >> 6, d = n & 63;
            if (z < 2) {
                size_t o = (((size_t)(b * NHEAD + h)) * S_LEN + s) * DK + d;
                uint32_t hi, lo;
                split2(c[mi][ni][0] * qs, c[mi][ni][1] * qs, hi, lo);
                *(uint32_t*)&dsthi[o] = hi; *(uint32_t*)&dstlo[o] = lo;
                split2(c[mi][ni][2] * qs, c[mi][ni][3] * qs, hi, lo);
                *(uint32_t*)&dsthi[o + 8 * DK] = hi; *(uint32_t*)&dstlo[o + 8 * DK] = lo;
            } else {
                // transposed store: VT[b][h][d][s]
#pragma unroll
                for (int v = 0; v < 4; v++) {
                    int dd = d + (v & 1);
                    int ss = s + (v >> 1) * 8;
                    float val = c[mi][ni][v];
                    bf hv = __float2bfloat16_rn(val);
                    bf lv = __float2bfloat16_rn(val - __bfloat162float(hv));
                    size_t o = (((size_t)(b * NHEAD + h)) * DK + dd) * S_LEN + ss;
                    dsthi[o] = hv; dstlo[o] = lv;
                }
            }
        }
    }
}

// Output projection: context(bf16 hi/lo) @ Wo^T -> fp32 out [M,N]
__global__ __launch_bounds__(256, 2)
void gemm_out(const bf* __restrict__ Whi, const bf* __restrict__ Wlo,
              float* __restrict__ out)
{
    extern __shared__ bf S[];
    float c[4][4][4];
    const int mBase = blockIdx.y * 128, nBase = blockIdx.x * 128;
    gemm_accum(g_Chi, g_Clo, Whi + (size_t)3 * MB, Wlo + (size_t)3 * MB,
               mBase, nBase, S, c);

    const int lane = threadIdx.x & 31, w = threadIdx.x >> 5;
    const int wm = w >> 2, wn = w & 3;
    const int g = lane >> 2, c2 = (lane & 3) * 2;

#pragma unroll
    for (int mi = 0; mi < 4; mi++) {
#pragma unroll
        for (int ni = 0; ni < 4; ni++) {
            int m = mBase + wm * 64 + mi * 16 + g;
            int n = nBase + wn * 32 + ni * 8 + c2;
            *(float2*)&out[(size_t)m * D_MODEL + n] =
                make_float2(c[mi][ni][0], c[mi][ni][1]);
            *(float2*)&out[(size_t)(m + 8) * D_MODEL + n] =
                make_float2(c[mi][ni][2], c[mi][ni][3]);
        }
    }
}

// ---------------- Flash attention (mma.sync), causal -------------------------
// Br=128, Bc=64, 256 threads, 8 warps; warp owns a 16-row strip.
// P kept in registers; K/V double-buffered cp.async; ldmatrix operand loads.
#define ASA 72                                // half stride
#define QH_OFF  0
#define QL_OFF  (128 * ASA)                   // 9216
#define ST_OFF  (2 * 128 * ASA)               // 18432
#define ST_SZ   (4 * 64 * ASA)                // 18432 halves per stage
#define ATTN_SMEM ((ST_OFF + 2 * ST_SZ) * 2)  // 110592 bytes

__global__ __launch_bounds__(256, 2)
void attn_tc(const bf* __restrict__ Qhi_g, const bf* __restrict__ Qlo_g,
             const bf* __restrict__ Khi_g, const bf* __restrict__ Klo_g,
             const bf* __restrict__ VThi_g, const bf* __restrict__ VTlo_g)
{
    extern __shared__ bf S[];
    const int tid = threadIdx.x;
    const int lane = tid & 31, w = tid >> 5;
    const int g = lane >> 2, c2 = (lane & 3) * 2;
    const int qt = (int)gridDim.x - 1 - (int)blockIdx.x;   // largest-first
    const int bh = blockIdx.y;
    const int q0 = qt * 128;
    const uint32_t sb = (uint32_t)__cvta_generic_to_shared(S);

    // ldmatrix lane-derived offsets
    const int a_r = lane & 15;
    const int a_c = (lane >> 4) * 8;
    const int b_r = ((lane >> 4) << 3) + (lane & 7);
    const int b_c = ((lane >> 3) & 1) * 8;

    const bf* Qhi = Qhi_g + (size_t)bh * S_LEN * DK;
    const bf* Qlo = Qlo_g + (size_t)bh * S_LEN * DK;
    const bf* Khi = Khi_g + (size_t)bh * S_LEN * DK;
    const bf* Klo = Klo_g + (size_t)bh * S_LEN * DK;
    const bf* VThi = VThi_g + (size_t)bh * DK * S_LEN;
    const bf* VTlo = VTlo_g + (size_t)bh * DK * S_LEN;

    auto issueKV = [&](int jt, int stage) {
        const int j0 = jt * 64;
        const uint32_t base = sb + (uint32_t)(ST_OFF + stage * ST_SZ) * 2;
#pragma unroll
        for (int i = 0; i < 2; i++) {
            int idx = tid + i * 256;              // 0..511
            int row = idx >> 3, d8 = (idx & 7) * 8;
            uint32_t db = base + (uint32_t)(row * ASA + d8) * 2;
            cpa16(db,                    Khi + (size_t)(j0 + row) * DK + d8);
            cpa16(db + 4608 * 2,         Klo + (size_t)(j0 + row) * DK + d8);
            cpa16(db + 9216 * 2,         VThi + (size_t)row * S_LEN + j0 + d8);
            cpa16(db + 13824 * 2,        VTlo + (size_t)row * S_LEN + j0 + d8);
        }
        cp_commit();
    };

    // group 0: Q tile (128 x 64 halves, hi+lo)
#pragma unroll
    for (int i = 0; i < 4; i++) {
        int idx = tid + i * 256;                  // 0..1023
        int row = idx >> 3, d8 = (idx & 7) * 8;
        uint32_t db = sb + (uint32_t)(row * ASA + d8) * 2;
        cpa16(db + QH_OFF * 2, Qhi + (size_t)(q0 + row) * DK + d8);
        cpa16(db + QL_OFF * 2, Qlo + (size_t)(q0 + row) * DK + d8);
    }
    cp_commit();

    const int jt_max = 2 * qt + 1;
    issueKV(0, 0);
    if (jt_max >= 1) issueKV(1, 1);

    float o_acc[8][4];
#pragma unroll
    for (int nt = 0; nt < 8; nt++)
#pragma unroll
        for (int v = 0; v < 4; v++) o_acc[nt][v] = 0.f;
    float m_a = -1e30f, m_b = -1e30f, l_a = 0.f, l_b = 0.f;

    const int growA = q0 + 16 * w + g;
    const int growB = growA + 8;

    for (int jt = 0; jt <= jt_max; jt++) {
        const int j0 = jt * 64;
        const int stage = jt & 1;
        const int KH = ST_OFF + stage * ST_SZ;
        const int KL = KH + 4608;
        const int VH = KH + 9216;
        const int VL = KH + 13824;

        if (jt == jt_max) cp_wait<0>(); else cp_wait<1>();
        __syncthreads();

        // ---- S = Q K^T (Q pre-scaled by 1/8) ----
        float sc[8][4];
#pragma unroll
        for (int nt = 0; nt < 8; nt++)
#pragma unroll
            for (int v = 0; v < 4; v++) sc[nt][v] = 0.f;

#pragma unroll
        for (int ks = 0; ks < 4; ks++) {
            const int kb = ks * 16;
            uint32_t qaddr = sb + (uint32_t)((16 * w + a_r) * ASA + kb + a_c) * 2;
            uint32_t ahi[4], alo[4];
            ldsm4(ahi, qaddr + QH_OFF * 2);
            ldsm4(alo, qaddr + QL_OFF * 2);
#pragma unroll
            for (int np = 0; np < 4; np++) {      // n-tile pairs
                uint32_t kaddr = sb + (uint32_t)((np * 16 + b_r) * ASA + kb + b_c) * 2;
                uint32_t bhi[4], blo[4];
                ldsm4(bhi, kaddr + KH * 2);
                ldsm4(blo, kaddr + KL * 2);
#pragma unroll
                for (int q = 0; q < 2; q++) {
                    const int nt = np * 2 + q;
                    mma_bf16(sc[nt], ahi, bhi + q * 2);
                    mma_bf16(sc[nt], ahi, blo + q * 2);
                    mma_bf16(sc[nt], alo, bhi + q * 2);
                }
            }
        }

        // ---- softmax (warp-local) + pack P into A-operand registers ----
        const bool diag = (jt >= 2 * qt);
        float mA = -1e30f, mB = -1e30f;
#pragma unroll
        for (int nt = 0; nt < 8; nt++) {
            int col = j0 + nt * 8 + c2;
            if (diag) {
                if (col     > growA) sc[nt][0] = -1e30f;
                if (col + 1 > growA) sc[nt][1] = -1e30f;
                if (col     > growB) sc[nt][2] = -1e30f;
                if (col + 1 > growB) sc[nt][3] = -1e30f;
            }
            mA = fmaxf(mA, fmaxf(sc[nt][0], sc[nt][1]));
            mB = fmaxf(mB, fmaxf(sc[nt][2], sc[nt][3]));
        }
#pragma unroll
        for (int o = 1; o < 4; o <<= 1) {
            mA = fmaxf(mA, __shfl_xor_sync(0xffffffffu, mA, o, 4));
            mB = fmaxf(mB, __shfl_xor_sync(0xffffffffu, mB, o, 4));
        }
        float mxA = fmaxf(m_a, mA), mxB = fmaxf(m_b, mB);
        float cfA = exp2f((m_a - mxA) * LOG2E);
        float cfB = exp2f((m_b - mxB) * LOG2E);
        float rsA = 0.f, rsB = 0.f;
        uint32_t pa_hi[8], pa_lo[8], pb_hi[8], pb_lo[8];  // rows g / g+8
#pragma unroll
        for (int nt = 0; nt < 8; nt++) {
            float p0 = exp2f((sc[nt][0] - mxA) * LOG2E);
            float p1 = exp2f((sc[nt][1] - mxA) * LOG2E);
            float p2 = exp2f((sc[nt][2] - mxB) * LOG2E);
            float p3 = exp2f((sc[nt][3] - mxB) * LOG2E);
            rsA += p0 + p1; rsB += p2 + p3;
            split2(p0, p1, pa_hi[nt], pa_lo[nt]);
            split2(p2, p3, pb_hi[nt], pb_lo[nt]);
        }
#pragma unroll
        for (int o = 1; o < 4; o <<= 1) {
            rsA += __shfl_xor_sync(0xffffffffu, rsA, o, 4);
            rsB += __shfl_xor_sync(0xffffffffu, rsB, o, 4);
        }
        l_a = l_a * cfA + rsA;  m_a = mxA;
        l_b = l_b * cfB + rsB;  m_b = mxB;
#pragma unroll
        for (int nt = 0; nt < 8; nt++) {
            o_acc[nt][0] *= cfA; o_acc[nt][1] *= cfA;
            o_acc[nt][2] *= cfB; o_acc[nt][3] *= cfB;
        }

        // ---- O += P V  (P from registers, V^T via ldmatrix) ----
#pragma unroll
        for (int ks = 0; ks < 4; ks++) {
            const int kb = ks * 16;
            uint32_t ahi[4] = {pa_hi[2*ks], pb_hi[2*ks], pa_hi[2*ks+1], pb_hi[2*ks+1]};
            uint32_t alo[4] = {pa_lo[2*ks], pb_lo[2*ks], pa_lo[2*ks+1], pb_lo[2*ks+1]};
#pragma unroll
            for (int np = 0; np < 4; np++) {
                uint32_t vaddr = sb + (uint32_t)((np * 16 + b_r) * ASA + kb + b_c) * 2;
                uint32_t bhi[4], blo[4];
                ldsm4(bhi, vaddr + VH * 2);
                ldsm4(blo, vaddr + VL * 2);
#pragma unroll
                for (int q = 0; q < 2; q++) {
                    const int nt = np * 2 + q;
                    mma_bf16(o_acc[nt], ahi, bhi + q * 2);
                    mma_bf16(o_acc[nt], ahi, blo + q * 2);
                    mma_bf16(o_acc[nt], alo, bhi + q * 2);
                }
            }
        }

        __syncthreads();                          // all warps done with this stage
        if (jt + 2 <= jt_max) issueKV(jt + 2, stage);
    }

    // ---- epilogue: normalize, split to bf16 hi/lo context [B,S,D] ----
    const float invA = 1.f / l_a, invB = 1.f / l_b;
    const int b = bh >> 4, h = bh & 15;
    const int sA = q0 + 16 * w + g;
#pragma unroll
    for (int nt = 0; nt < 8; nt++) {
        int col = h * DK + nt * 8 + c2;
        uint32_t hi, lo;
        split2(o_acc[nt][0] * invA, o_acc[nt][1] * invA, hi, lo);
        size_t o = ((size_t)(b * S_LEN + sA)) * D_MODEL + col;
        *(uint32_t*)&g_Chi[o] = hi; *(uint32_t*)&g_Clo[o] = lo;
        split2(o_acc[nt][2] * invB, o_acc[nt][3] * invB, hi, lo);
        size_t o2 = ((size_t)(b * S_LEN + sA + 8)) * D_MODEL + col;
        *(uint32_t*)&g_Chi[o2] = hi; *(uint32_t*)&g_Clo[o2] = lo;
    }
}

// ---------------------------------------------------------------------------
extern "C" void kernel_launch(void* const* d_in, const int* in_sizes, int n_in,
                              void* d_out, int out_size)
{
    const float* x  = (const float*)d_in[0];
    const float* Wq = (const float*)d_in[1];
    const float* Wk = (const float*)d_in[2];
    const float* Wv = (const float*)d_in[3];
    const float* Wo = (const float*)d_in[4];
    float* out = (float*)d_out;

    bf *pXhi, *pXlo, *pWhi, *pWlo;
    bf *pQhi, *pQlo, *pKhi, *pKlo, *pVThi, *pVTlo;
    cudaGetSymbolAddress((void**)&pXhi, g_Xhi);
    cudaGetSymbolAddress((void**)&pXlo, g_Xlo);
    cudaGetSymbolAddress((void**)&pWhi, g_Whi);
    cudaGetSymbolAddress((void**)&pWlo, g_Wlo);
    cudaGetSymbolAddress((void**)&pQhi, g_Qhi);
    cudaGetSymbolAddress((void**)&pQlo, g_Qlo);
    cudaGetSymbolAddress((void**)&pKhi, g_Khi);
    cudaGetSymbolAddress((void**)&pKlo, g_Klo);
    cudaGetSymbolAddress((void**)&pVThi, g_VThi);
    cudaGetSymbolAddress((void**)&pVTlo, g_VTlo);

    static bool configured = false;
    if (!configured) {
        cudaFuncSetAttribute(gemm_qkv, cudaFuncAttributeMaxDynamicSharedMemorySize, GEMM_SMEM);
        cudaFuncSetAttribute(gemm_out, cudaFuncAttributeMaxDynamicSharedMemorySize, GEMM_SMEM);
        cudaFuncSetAttribute(attn_tc,  cudaFuncAttributeMaxDynamicSharedMemorySize, ATTN_SMEM);
        configured = true;
    }

    // pre-pass: split all inputs into bf16 hi/lo (single launch)
    split_all<<<4096, 256>>>((const float4*)x, (const float4*)Wq, (const float4*)Wk,
                             (const float4*)Wv, (const float4*)Wo,
                             (uint2*)pXhi, (uint2*)pXlo, (uint2*)pWhi, (uint2*)pWlo);

    dim3 qkvGrid(D_MODEL / 128, MTOT / 128, 3);   // (8, 32, 3)
    gemm_qkv<<<qkvGrid, 256, GEMM_SMEM>>>(pXhi, pXlo, pWhi, pWlo);

    dim3 aGrid(S_LEN / 128, BATCH * NHEAD);       // (16, 32)
    attn_tc<<<aGrid, 256, ATTN_SMEM>>>(pQhi, pQlo, pKhi, pKlo, pVThi, pVTlo);

    dim3 oGrid(D_MODEL / 128, MTOT / 128);        // (8, 32)
    gemm_out<<<oGrid, 256, GEMM_SMEM>>>(pWhi, pWlo, out);
}